// round 11
// baseline (speedup 1.0000x reference)
#include <cuda_runtime.h>
#include <cuda_bf16.h>
#include <math.h>
#include <stdint.h>

#define B_  256
#define T_  512
#define D_  128
#define H_  256
#define G_  768
#define C_  10

// ---------------- warp-mma helpers (sm_80+ baseline; compiles for plain sm_103) ---
__device__ __forceinline__ uint32_t smem_u32(const void* p) {
    uint32_t a;
    asm("{ .reg .u64 t; cvta.to.shared.u64 t, %1; cvt.u32.u64 %0, t; }" : "=r"(a) : "l"(p));
    return a;
}
#define LDSM4(r0, r1, r2, r3, addr) \
    asm volatile("ldmatrix.sync.aligned.m8n8.x4.shared.b16 {%0,%1,%2,%3}, [%4];" \
        : "=r"(r0), "=r"(r1), "=r"(r2), "=r"(r3) : "r"(addr))
#define LDSM2(r0, r1, addr) \
    asm volatile("ldmatrix.sync.aligned.m8n8.x2.shared.b16 {%0,%1}, [%2];" \
        : "=r"(r0), "=r"(r1) : "r"(addr))
#define MMA16816(c, a, b0v, b1v) \
    asm volatile("mma.sync.aligned.m16n8k16.row.col.f32.bf16.bf16.f32 " \
        "{%0,%1,%2,%3},{%4,%5,%6,%7},{%8,%9},{%0,%1,%2,%3};" \
        : "+f"((c)[0]), "+f"((c)[1]), "+f"((c)[2]), "+f"((c)[3]) \
        : "r"((a)[0]), "r"((a)[1]), "r"((a)[2]), "r"((a)[3]), "r"(b0v), "r"(b1v))

// ---------------- scratch (device globals; no allocation allowed) ----------------
__device__ float g_gi[(size_t)B_ * T_ * G_];            // gi for current layer
__device__ __nv_bfloat16 g_seqhi[(size_t)T_ * B_ * H_]; // layer-0 h sequence, bf16 hi
__device__ __nv_bfloat16 g_seqlo[(size_t)T_ * B_ * H_]; // layer-0 h sequence, bf16 lo
__device__ __nv_bfloat16 g_hbhi[2][B_ * H_];            // ping-pong h (bf16 hi)
__device__ __nv_bfloat16 g_hblo[2][B_ * H_];            // ping-pong h (bf16 lo)
__device__ float g_hlast[B_ * H_];                      // final fp32 h for the FC
__device__ volatile unsigned g_gen[64];                 // per-pair barrier generation
__device__ unsigned g_cnt[64];                          // per-pair arrival counter
__device__ __nv_bfloat16 g_ahi[(size_t)131072 * 128];   // x split (layer-0 gi GEMM)
__device__ __nv_bfloat16 g_alo[(size_t)131072 * 128];
__device__ __nv_bfloat16 g_whi[G_ * H_];
__device__ __nv_bfloat16 g_wlo[G_ * H_];

// ---------------- reset barrier state (graph-replay safe) --------------------------
__global__ void reset_bar()
{
    const int i = threadIdx.x;
    if (i < 64) { g_cnt[i] = 0u; ((unsigned*)g_gen)[i] = 0u; }
}

// ---------------- fp32 -> (bf16 hi, bf16 lo) split ---------------------------------
__global__ void split_bf16(const float* __restrict__ s, __nv_bfloat16* __restrict__ hi,
                           __nv_bfloat16* __restrict__ lo, int n4)
{
    const int i = blockIdx.x * blockDim.x + threadIdx.x;
    if (i >= n4) return;
    const float4 v = ((const float4*)s)[i];
    __nv_bfloat16 h0 = __float2bfloat16(v.x);
    __nv_bfloat16 h1 = __float2bfloat16(v.y);
    __nv_bfloat16 h2 = __float2bfloat16(v.z);
    __nv_bfloat16 h3 = __float2bfloat16(v.w);
    __nv_bfloat16 l0 = __float2bfloat16(v.x - __bfloat162float(h0));
    __nv_bfloat16 l1 = __float2bfloat16(v.y - __bfloat162float(h1));
    __nv_bfloat16 l2 = __float2bfloat16(v.z - __bfloat162float(h2));
    __nv_bfloat16 l3 = __float2bfloat16(v.w - __bfloat162float(h3));
    __nv_bfloat162* hp = (__nv_bfloat162*)hi;
    __nv_bfloat162* lp = (__nv_bfloat162*)lo;
    hp[i * 2 + 0] = __nv_bfloat162(h0, h1);
    hp[i * 2 + 1] = __nv_bfloat162(h2, h3);
    lp[i * 2 + 0] = __nv_bfloat162(l0, l1);
    lp[i * 2 + 1] = __nv_bfloat162(l2, l3);
}

// ---------------- split-bf16 HMMA GEMM (R8/R9-proven, unchanged) -------------------
__global__ void __launch_bounds__(256, 1) mma_gemm(
    const __nv_bfloat16* __restrict__ Ahi, const __nv_bfloat16* __restrict__ Alo,
    const __nv_bfloat16* __restrict__ Whi, const __nv_bfloat16* __restrict__ Wlo,
    const float* __restrict__ bias, float* __restrict__ C, int K)
{
    extern __shared__ char smem[];
    const int KS = K + 8;
    const int strB = KS * 2;
    char* sAhi = smem;
    char* sAlo = sAhi + 128 * strB;
    char* sWhi = sAlo + 128 * strB;
    char* sWlo = sWhi + 64 * strB;

    const int tid = threadIdx.x;
    const int n0 = blockIdx.x * 64;
    const int m0 = blockIdx.y * 128;

    const int cpr = K >> 3;
    for (int c = tid; c < 128 * cpr; c += 256) {
        const int r = c / cpr, kc = c % cpr;
        const size_t src = (size_t)(m0 + r) * K + kc * 8;
        *(uint4*)(sAhi + r * strB + kc * 16) = *(const uint4*)(Ahi + src);
        *(uint4*)(sAlo + r * strB + kc * 16) = *(const uint4*)(Alo + src);
    }
    for (int c = tid; c < 64 * cpr; c += 256) {
        const int r = c / cpr, kc = c % cpr;
        const size_t src = (size_t)(n0 + r) * K + kc * 8;
        *(uint4*)(sWhi + r * strB + kc * 16) = *(const uint4*)(Whi + src);
        *(uint4*)(sWlo + r * strB + kc * 16) = *(const uint4*)(Wlo + src);
    }
    __syncthreads();

    const int wid = tid >> 5, lane = tid & 31;
    const int mw = wid >> 1, nw = wid & 1;

    float acc[2][4][4];
#pragma unroll
    for (int mt = 0; mt < 2; mt++)
#pragma unroll
        for (int nt = 0; nt < 4; nt++)
#pragma unroll
            for (int q = 0; q < 4; q++) acc[mt][nt][q] = 0.f;

    const int aRow = mw * 32 + (lane & 15);
    const int aKof = (lane >> 4) * 16;
    const int bRow = nw * 32 + (lane & 7) + ((lane >> 4) << 3);
    const int bKof = ((lane >> 3) & 1) * 16;

    const uint32_t uAhi = smem_u32(sAhi), uAlo = smem_u32(sAlo);
    const uint32_t uWhi = smem_u32(sWhi), uWlo = smem_u32(sWlo);

    const int nks = K >> 4;
    for (int ks = 0; ks < nks; ks++) {
        const int kb = ks * 32;
        uint32_t ah[2][4], al[2][4], bh[4][2], bl[4][2];
#pragma unroll
        for (int mt = 0; mt < 2; mt++) {
            const uint32_t ra = (uint32_t)((aRow + mt * 16) * strB + kb + aKof);
            LDSM4(ah[mt][0], ah[mt][1], ah[mt][2], ah[mt][3], uAhi + ra);
            LDSM4(al[mt][0], al[mt][1], al[mt][2], al[mt][3], uAlo + ra);
        }
#pragma unroll
        for (int np = 0; np < 2; np++) {
            const uint32_t rb = (uint32_t)((bRow + np * 16) * strB + kb + bKof);
            uint32_t t0, t1, t2, t3;
            LDSM4(t0, t1, t2, t3, uWhi + rb);
            bh[np * 2][0] = t0; bh[np * 2][1] = t1;
            bh[np * 2 + 1][0] = t2; bh[np * 2 + 1][1] = t3;
            LDSM4(t0, t1, t2, t3, uWlo + rb);
            bl[np * 2][0] = t0; bl[np * 2][1] = t1;
            bl[np * 2 + 1][0] = t2; bl[np * 2 + 1][1] = t3;
        }
#pragma unroll
        for (int mt = 0; mt < 2; mt++)
#pragma unroll
            for (int nt = 0; nt < 4; nt++) {
                MMA16816(acc[mt][nt], ah[mt], bh[nt][0], bh[nt][1]);
                MMA16816(acc[mt][nt], ah[mt], bl[nt][0], bl[nt][1]);
                MMA16816(acc[mt][nt], al[mt], bh[nt][0], bh[nt][1]);
            }
    }

#pragma unroll
    for (int mt = 0; mt < 2; mt++)
#pragma unroll
        for (int nt = 0; nt < 4; nt++) {
            const int row = m0 + mw * 32 + mt * 16 + (lane >> 2);
            const int col = n0 + nw * 32 + nt * 8 + (lane & 3) * 2;
            const float b0 = bias[col], b1 = bias[col + 1];
            float2 o0, o1;
            o0.x = acc[mt][nt][0] + b0; o0.y = acc[mt][nt][1] + b1;
            o1.x = acc[mt][nt][2] + b0; o1.y = acc[mt][nt][3] + b1;
            *(float2*)&C[(size_t)row * G_ + col]       = o0;
            *(float2*)&C[(size_t)(row + 8) * G_ + col] = o1;
        }
}

// ---------------- dual-chain persistent GRU scan (HMMA) ----------------------------
// 64 CTAs x 256 threads. CTA (pairid 0..1, jblk 0..31) serves TWO independent batch
// groups {2p, 2p+1} (64 batches each) for hidden dims [j0, j0+8). One barrier per
// iteration per pair; the wait is separated from the arrive by a full phase of
// independent work, hiding barrier settle latency. GEMM/gates/exchange = R9 logic.
// smem bytes: swhi 0 /12672, swlo 12672, shhi 25344 /33792, shlo 59136,
//             part 92928 /12800, gis 105728 /25600 (2 ph x 2 buf x 1600 f),
//             hst 131328 /4608 (2 ph x 576 f), bsl 135936 /96. total 136032.
__global__ void __launch_bounds__(256, 1) gru_scan_dual(
    const float* __restrict__ gi, const float* __restrict__ Whh,
    const float* __restrict__ bhh,
    __nv_bfloat16* __restrict__ seqhi, __nv_bfloat16* __restrict__ seqlo, int tmajor)
{
    extern __shared__ char smc[];
    __nv_bfloat16* swhi = (__nv_bfloat16*)smc;
    __nv_bfloat16* swlo = (__nv_bfloat16*)(smc + 12672);
    char* shhi_c = smc + 25344;
    char* shlo_c = smc + 59136;
    float* part = (float*)(smc + 92928);
    float* gisb = (float*)(smc + 105728);
    float* hstb = (float*)(smc + 131328);
    float* bsl  = (float*)(smc + 135936);

    const int tid = threadIdx.x;
    const int cta = blockIdx.x;
    const int jblk = cta & 31;
    const int pairid = cta >> 5;
    const int j0 = jblk * 8;
    const int grp = pairid * 32;       // padded barrier slot
    const int b0base = pairid * 128;

    // ---- persistent Whh slice, split hi/lo ----
    for (int idx = tid; idx < 24 * 256; idx += 256) {
        const int row = idx >> 8, k = idx & 255;
        const float v = Whh[(size_t)((row >> 3) * H_ + j0 + (row & 7)) * H_ + k];
        const __nv_bfloat16 hi = __float2bfloat16(v);
        swhi[row * 264 + k] = hi;
        swlo[row * 264 + k] = __float2bfloat16(v - __bfloat162float(hi));
    }
    if (tid < 24) bsl[tid] = bhh[(tid >> 3) * H_ + j0 + (tid & 7)];
    for (int idx = tid; idx < 1152; idx += 256) hstb[idx] = 0.f;

    const int w = tid >> 5, lane = tid & 31;
    const int mt = w & 3, kh = w >> 2;

    const int aoff   = (mt * 16 + (lane & 15)) * 528 + (lane >> 4) * 16;
    const int boff01 = ((lane & 7) + ((lane >> 4) << 3)) * 528 + ((lane >> 3) & 1) * 16;
    const int boff2  = (16 + (lane & 7)) * 528 + ((lane >> 3) & 1) * 16;
    const uint32_t uAhi = smem_u32(shhi_c), uAlo = smem_u32(shlo_c);
    const uint32_t uWhi = smem_u32(smc), uWlo = smem_u32(smc + 12672);

    // per-thread gi staging map (6 elements per phase; b relative to group base)
    int gq_b[6], gq_sm[6], gq_col[6];
#pragma unroll
    for (int q = 0; q < 6; q++) {
        const int idx = tid + 256 * q;
        const int b = idx / 24, gg = idx % 24;
        gq_b[q] = b;
        gq_sm[q] = b * 25 + gg;
        gq_col[q] = (gg >> 3) * H_ + j0 + (gg & 7);
    }
    float greg[2][6];
#pragma unroll
    for (int ph = 0; ph < 2; ph++) {
        const int b0 = b0base + ph * 64;
#pragma unroll
        for (int q = 0; q < 6; q++) {
            const size_t row = tmajor ? ((size_t)0 * B_ + b0 + gq_b[q])
                                      : ((size_t)(b0 + gq_b[q]) * T_ + 0);
            greg[ph][q] = gi[row * G_ + gq_col[q]];
        }
#pragma unroll
        for (int q = 0; q < 6; q++) gisb[ph * 3200 + gq_sm[q]] = greg[ph][q];
    }
    __syncthreads();

    for (int t = 0; t < T_; t++) {
        // ---- wait for iteration t-1 of this pair (settles under prior work) ----
        if (tid == 0) {
            while (g_gen[grp] < (unsigned)t) {}
            __threadfence();                 // L1 inval before reading peers' h
        }
        __syncthreads();
        const int cur = t & 1, nxt = cur ^ 1;

#pragma unroll
        for (int ph = 0; ph < 2; ph++) {
            const int b0 = b0base + ph * 64;
            const float* gcur = gisb + ph * 3200 + cur * 1600;
            float* gnxt = gisb + ph * 3200 + nxt * 1600;
            float* hstp = hstb + ph * 576;

            // ---- stage h_prev hi/lo for this group ----
            if (t == 0) {
                const uint4 z4 = make_uint4(0u, 0u, 0u, 0u);
#pragma unroll
                for (int q = 0; q < 8; q++) {
                    const int v = tid + 256 * q;
                    const int b = v >> 5, c = v & 31;
                    *(uint4*)(shhi_c + b * 528 + c * 16) = z4;
                    *(uint4*)(shlo_c + b * 528 + c * 16) = z4;
                }
            } else {
#pragma unroll
                for (int q = 0; q < 8; q++) {
                    const int v = tid + 256 * q;
                    const int b = v >> 5, c = v & 31;
                    *(uint4*)(shhi_c + b * 528 + c * 16) =
                        *(const uint4*)&g_hbhi[cur][(b0 + b) * H_ + c * 8];
                    *(uint4*)(shlo_c + b * 528 + c * 16) =
                        *(const uint4*)&g_hblo[cur][(b0 + b) * H_ + c * 8];
                }
            }
            // ---- prefetch gi(t+1) for this group ----
            {
                const int tn = (t + 1 < T_) ? (t + 1) : t;
#pragma unroll
                for (int q = 0; q < 6; q++) {
                    const size_t row = tmajor ? ((size_t)tn * B_ + b0 + gq_b[q])
                                              : ((size_t)(b0 + gq_b[q]) * T_ + tn);
                    greg[ph][q] = __ldg(&gi[row * G_ + gq_col[q]]);
                }
            }
            __syncthreads();

            // ---- HMMA GEMM: gh[64][24] over K-half kh, 3 split passes ----
            float a0[4] = {0.f, 0.f, 0.f, 0.f};
            float a1[4] = {0.f, 0.f, 0.f, 0.f};
            float a2[4] = {0.f, 0.f, 0.f, 0.f};
#pragma unroll
            for (int ks = 0; ks < 8; ks++) {
                const int kb = kh * 256 + ks * 32;
                uint32_t ah[4], al[4], bh01[4], bl01[4], bh2[2], bl2[2];
                LDSM4(ah[0], ah[1], ah[2], ah[3], uAhi + aoff + kb);
                LDSM4(al[0], al[1], al[2], al[3], uAlo + aoff + kb);
                LDSM4(bh01[0], bh01[1], bh01[2], bh01[3], uWhi + boff01 + kb);
                LDSM2(bh2[0], bh2[1], uWhi + boff2 + kb);
                LDSM4(bl01[0], bl01[1], bl01[2], bl01[3], uWlo + boff01 + kb);
                LDSM2(bl2[0], bl2[1], uWlo + boff2 + kb);
                MMA16816(a0, ah, bh01[0], bh01[1]);
                MMA16816(a1, ah, bh01[2], bh01[3]);
                MMA16816(a2, ah, bh2[0], bh2[1]);
                MMA16816(a0, ah, bl01[0], bl01[1]);
                MMA16816(a1, ah, bl01[2], bl01[3]);
                MMA16816(a2, ah, bl2[0], bl2[1]);
                MMA16816(a0, al, bh01[0], bh01[1]);
                MMA16816(a1, al, bh01[2], bh01[3]);
                MMA16816(a2, al, bh2[0], bh2[1]);
            }
            {
                float* p = &part[(kh * 64 + mt * 16 + (lane >> 2)) * 25];
                const int col = 2 * (lane & 3);
                p[col] = a0[0];      p[col + 1] = a0[1];
                p[8 + col] = a1[0];  p[9 + col] = a1[1];
                p[16 + col] = a2[0]; p[17 + col] = a2[1];
                float* p8 = p + 8 * 25;
                p8[col] = a0[2];      p8[col + 1] = a0[3];
                p8[8 + col] = a1[2];  p8[9 + col] = a1[3];
                p8[16 + col] = a2[2]; p8[17 + col] = a2[3];
            }
#pragma unroll
            for (int q = 0; q < 6; q++) gnxt[gq_sm[q]] = greg[ph][q];
            __syncthreads();

            // ---- reduce 2 partials + gates (2 (b,jj) per thread, exclusive) ----
#pragma unroll
            for (int p = 0; p < 2; p++) {
                const int pr = tid + p * 256;
                const int b = pr & 63, jj = pr >> 6;
                const float* p0 = &part[b * 25];
                const float* p1 = &part[(64 + b) * 25];
                const float sr = bsl[jj] + p0[jj] + p1[jj] + gcur[b * 25 + jj];
                const float sz = bsl[8 + jj] + p0[8 + jj] + p1[8 + jj]
                               + gcur[b * 25 + 8 + jj];
                const float sn = bsl[16 + jj] + p0[16 + jj] + p1[16 + jj];
                const float r = __fdividef(1.f, 1.f + __expf(-sr));
                const float z = __fdividef(1.f, 1.f + __expf(-sz));
                const float a = gcur[b * 25 + 16 + jj] + r * sn;
                const float n = __fdividef(2.f, 1.f + __expf(-2.f * a)) - 1.f;
                const float hold = hstp[b * 9 + jj];
                hstp[b * 9 + jj] = (1.f - z) * n + z * hold;
            }
            __syncthreads();

            // ---- convert own slice to hi/lo and publish (threads 0..63) ----
            if (tid < 64) {
                const int b = tid;
                union { __nv_bfloat16 a8[8]; uint4 u; } uhi, ulo;
                float f[8];
#pragma unroll
                for (int j = 0; j < 8; j++) {
                    f[j] = hstp[b * 9 + j];
                    uhi.a8[j] = __float2bfloat16(f[j]);
                    ulo.a8[j] = __float2bfloat16(f[j] - __bfloat162float(uhi.a8[j]));
                }
                const size_t go = (size_t)(b0 + b) * H_ + j0;
                *(uint4*)&g_hbhi[nxt][go] = uhi.u;
                *(uint4*)&g_hblo[nxt][go] = ulo.u;
                if (seqhi) {
                    const size_t so = ((size_t)t * B_ + b0 + b) * H_ + j0;
                    *(uint4*)&seqhi[so] = uhi.u;
                    *(uint4*)&seqlo[so] = ulo.u;
                }
                if (t == T_ - 1) {
                    *(float4*)&g_hlast[go]     = make_float4(f[0], f[1], f[2], f[3]);
                    *(float4*)&g_hlast[go + 4] = make_float4(f[4], f[5], f[6], f[7]);
                }
            }
            __syncthreads();
        }

        // ---- single arrive per iteration (wait happens next iteration) ----
        __threadfence();
        __syncthreads();
        if (tid == 0) {
            if (atomicAdd(&g_cnt[grp], 1u) == 31u) {
                g_cnt[grp] = 0u;
                __threadfence();
                g_gen[grp] = (unsigned)(t + 1);
            }
        }
    }
}

// ---------------- final FC: out[256,10] = h @ Wfc^T + bfc -------------------------
__global__ void fc_kernel(const float* __restrict__ h, const float* __restrict__ Wfc,
                          const float* __restrict__ bfc, float* __restrict__ out)
{
    const int b = blockIdx.x;
    const int lane = threadIdx.x;
    float hv[8];
#pragma unroll
    for (int i = 0; i < 8; i++) hv[i] = h[b * H_ + lane + 32 * i];
    for (int cc = 0; cc < C_; cc++) {
        float s = 0.f;
#pragma unroll
        for (int i = 0; i < 8; i++) s += hv[i] * Wfc[cc * H_ + lane + 32 * i];
#pragma unroll
        for (int o = 16; o > 0; o >>= 1) s += __shfl_down_sync(0xffffffffu, s, o);
        if (lane == 0) out[b * C_ + cc] = s + bfc[cc];
    }
}

// ---------------- launch ----------------------------------------------------------
extern "C" void kernel_launch(void* const* d_in, const int* in_sizes, int n_in,
                              void* d_out, int out_size)
{
    (void)in_sizes; (void)n_in; (void)out_size;
    const float* x    = (const float*)d_in[0];
    const float* Wih0 = (const float*)d_in[1];
    const float* Whh0 = (const float*)d_in[2];
    const float* bih0 = (const float*)d_in[3];
    const float* bhh0 = (const float*)d_in[4];
    const float* Wih1 = (const float*)d_in[5];
    const float* Whh1 = (const float*)d_in[6];
    const float* bih1 = (const float*)d_in[7];
    const float* bhh1 = (const float*)d_in[8];
    const float* Wfc  = (const float*)d_in[9];
    const float* bfc  = (const float*)d_in[10];
    float* out = (float*)d_out;

    float *p_gi, *p_hl;
    __nv_bfloat16 *p_ahi, *p_alo, *p_whi, *p_wlo, *p_shi, *p_slo;
    cudaGetSymbolAddress((void**)&p_gi, g_gi);
    cudaGetSymbolAddress((void**)&p_hl, g_hlast);
    cudaGetSymbolAddress((void**)&p_ahi, g_ahi);
    cudaGetSymbolAddress((void**)&p_alo, g_alo);
    cudaGetSymbolAddress((void**)&p_whi, g_whi);
    cudaGetSymbolAddress((void**)&p_wlo, g_wlo);
    cudaGetSymbolAddress((void**)&p_shi, g_seqhi);
    cudaGetSymbolAddress((void**)&p_slo, g_seqlo);

    const int scan_smem = 136032;
    cudaFuncSetAttribute(gru_scan_dual, cudaFuncAttributeMaxDynamicSharedMemorySize, scan_smem);
    const int gemm_smem1 = 384 * (256 + 8) * 2;
    const int gemm_smem0 = 384 * (128 + 8) * 2;
    cudaFuncSetAttribute(mma_gemm, cudaFuncAttributeMaxDynamicSharedMemorySize, gemm_smem1);

    const dim3 gtile(12, 1024);

    // ---- layer 0: gi0 = x @ Wih0^T + bih0 (rows b*T+t) ----
    split_bf16<<<(131072 * 128 / 4 + 255) / 256, 256>>>(x, p_ahi, p_alo, 131072 * 128 / 4);
    split_bf16<<<(G_ * D_ / 4 + 255) / 256, 256>>>(Wih0, p_whi, p_wlo, G_ * D_ / 4);
    mma_gemm<<<gtile, 256, gemm_smem0>>>(p_ahi, p_alo, p_whi, p_wlo, bih0, p_gi, D_);
    reset_bar<<<1, 64>>>();
    gru_scan_dual<<<64, 256, scan_smem>>>(p_gi, Whh0, bhh0, p_shi, p_slo, /*tmajor=*/0);

    // ---- layer 1: gi1 = h1 @ Wih1^T + bih1 (rows t*B+b, hi/lo straight from scan) ----
    split_bf16<<<(G_ * H_ / 4 + 255) / 256, 256>>>(Wih1, p_whi, p_wlo, G_ * H_ / 4);
    mma_gemm<<<gtile, 256, gemm_smem1>>>(p_shi, p_slo, p_whi, p_wlo, bih1, p_gi, H_);
    reset_bar<<<1, 64>>>();
    gru_scan_dual<<<64, 256, scan_smem>>>(p_gi, Whh1, bhh1, nullptr, nullptr, /*tmajor=*/1);

    // classifier on final hidden state
    fc_kernel<<<B_, 32>>>(p_hl, Wfc, bfc, out);
}

// round 12
// speedup vs baseline: 1.4530x; 1.4530x over previous
#include <cuda_runtime.h>
#include <cuda_bf16.h>
#include <math.h>
#include <stdint.h>

#define B_  256
#define T_  512
#define D_  128
#define H_  256
#define G_  768
#define C_  10

#define NCTA_SCAN 128
#define GRP_CTAS  32

// ---------------- warp-mma helpers (sm_80+ baseline; compiles for plain sm_103) ---
__device__ __forceinline__ uint32_t smem_u32(const void* p) {
    uint32_t a;
    asm("{ .reg .u64 t; cvta.to.shared.u64 t, %1; cvt.u32.u64 %0, t; }" : "=r"(a) : "l"(p));
    return a;
}
#define LDSM4(r0, r1, r2, r3, addr) \
    asm volatile("ldmatrix.sync.aligned.m8n8.x4.shared.b16 {%0,%1,%2,%3}, [%4];" \
        : "=r"(r0), "=r"(r1), "=r"(r2), "=r"(r3) : "r"(addr))
#define LDSM2(r0, r1, addr) \
    asm volatile("ldmatrix.sync.aligned.m8n8.x2.shared.b16 {%0,%1}, [%2];" \
        : "=r"(r0), "=r"(r1) : "r"(addr))
#define MMA16816(c, a, b0v, b1v) \
    asm volatile("mma.sync.aligned.m16n8k16.row.col.f32.bf16.bf16.f32 " \
        "{%0,%1,%2,%3},{%4,%5,%6,%7},{%8,%9},{%0,%1,%2,%3};" \
        : "+f"((c)[0]), "+f"((c)[1]), "+f"((c)[2]), "+f"((c)[3]) \
        : "r"((a)[0]), "r"((a)[1]), "r"((a)[2]), "r"((a)[3]), "r"(b0v), "r"(b1v))

// ---------------- scratch (device globals; no allocation allowed) ----------------
__device__ float g_gi[(size_t)B_ * T_ * G_];            // gi for current layer
__device__ __nv_bfloat16 g_seqhi[(size_t)T_ * B_ * H_]; // layer-0 h sequence, bf16 hi
__device__ __nv_bfloat16 g_seqlo[(size_t)T_ * B_ * H_]; // layer-0 h sequence, bf16 lo
__device__ __nv_bfloat16 g_hbhi[2][B_ * H_];            // ping-pong h (bf16 hi)
__device__ __nv_bfloat16 g_hblo[2][B_ * H_];            // ping-pong h (bf16 lo)
__device__ float g_hlast[B_ * H_];                      // final fp32 h for the FC
__device__ volatile unsigned g_gen[4 * 32];             // per-group barrier generation
__device__ unsigned g_cnt[4 * 32];                      // per-group arrival counter
__device__ __nv_bfloat16 g_ahi[(size_t)131072 * 128];   // x split (layer-0 gi GEMM)
__device__ __nv_bfloat16 g_alo[(size_t)131072 * 128];
__device__ __nv_bfloat16 g_whi[G_ * H_];
__device__ __nv_bfloat16 g_wlo[G_ * H_];

// ---------------- fp32 -> (bf16 hi, bf16 lo) split ---------------------------------
__global__ void split_bf16(const float* __restrict__ s, __nv_bfloat16* __restrict__ hi,
                           __nv_bfloat16* __restrict__ lo, int n4)
{
    const int i = blockIdx.x * blockDim.x + threadIdx.x;
    if (i >= n4) return;
    const float4 v = ((const float4*)s)[i];
    __nv_bfloat16 h0 = __float2bfloat16(v.x);
    __nv_bfloat16 h1 = __float2bfloat16(v.y);
    __nv_bfloat16 h2 = __float2bfloat16(v.z);
    __nv_bfloat16 h3 = __float2bfloat16(v.w);
    __nv_bfloat16 l0 = __float2bfloat16(v.x - __bfloat162float(h0));
    __nv_bfloat16 l1 = __float2bfloat16(v.y - __bfloat162float(h1));
    __nv_bfloat16 l2 = __float2bfloat16(v.z - __bfloat162float(h2));
    __nv_bfloat16 l3 = __float2bfloat16(v.w - __bfloat162float(h3));
    __nv_bfloat162* hp = (__nv_bfloat162*)hi;
    __nv_bfloat162* lp = (__nv_bfloat162*)lo;
    hp[i * 2 + 0] = __nv_bfloat162(h0, h1);
    hp[i * 2 + 1] = __nv_bfloat162(h2, h3);
    lp[i * 2 + 0] = __nv_bfloat162(l0, l1);
    lp[i * 2 + 1] = __nv_bfloat162(l2, l3);
}

// ---------------- split-bf16 HMMA GEMM (R8/R9-proven, unchanged) -------------------
__global__ void __launch_bounds__(256, 1) mma_gemm(
    const __nv_bfloat16* __restrict__ Ahi, const __nv_bfloat16* __restrict__ Alo,
    const __nv_bfloat16* __restrict__ Whi, const __nv_bfloat16* __restrict__ Wlo,
    const float* __restrict__ bias, float* __restrict__ C, int K)
{
    extern __shared__ char smem[];
    const int KS = K + 8;
    const int strB = KS * 2;
    char* sAhi = smem;
    char* sAlo = sAhi + 128 * strB;
    char* sWhi = sAlo + 128 * strB;
    char* sWlo = sWhi + 64 * strB;

    const int tid = threadIdx.x;
    const int n0 = blockIdx.x * 64;
    const int m0 = blockIdx.y * 128;

    const int cpr = K >> 3;
    for (int c = tid; c < 128 * cpr; c += 256) {
        const int r = c / cpr, kc = c % cpr;
        const size_t src = (size_t)(m0 + r) * K + kc * 8;
        *(uint4*)(sAhi + r * strB + kc * 16) = *(const uint4*)(Ahi + src);
        *(uint4*)(sAlo + r * strB + kc * 16) = *(const uint4*)(Alo + src);
    }
    for (int c = tid; c < 64 * cpr; c += 256) {
        const int r = c / cpr, kc = c % cpr;
        const size_t src = (size_t)(n0 + r) * K + kc * 8;
        *(uint4*)(sWhi + r * strB + kc * 16) = *(const uint4*)(Whi + src);
        *(uint4*)(sWlo + r * strB + kc * 16) = *(const uint4*)(Wlo + src);
    }
    __syncthreads();

    const int wid = tid >> 5, lane = tid & 31;
    const int mw = wid >> 1, nw = wid & 1;

    float acc[2][4][4];
#pragma unroll
    for (int mt = 0; mt < 2; mt++)
#pragma unroll
        for (int nt = 0; nt < 4; nt++)
#pragma unroll
            for (int q = 0; q < 4; q++) acc[mt][nt][q] = 0.f;

    const int aRow = mw * 32 + (lane & 15);
    const int aKof = (lane >> 4) * 16;
    const int bRow = nw * 32 + (lane & 7) + ((lane >> 4) << 3);
    const int bKof = ((lane >> 3) & 1) * 16;

    const uint32_t uAhi = smem_u32(sAhi), uAlo = smem_u32(sAlo);
    const uint32_t uWhi = smem_u32(sWhi), uWlo = smem_u32(sWlo);

    const int nks = K >> 4;
    for (int ks = 0; ks < nks; ks++) {
        const int kb = ks * 32;
        uint32_t ah[2][4], al[2][4], bh[4][2], bl[4][2];
#pragma unroll
        for (int mt = 0; mt < 2; mt++) {
            const uint32_t ra = (uint32_t)((aRow + mt * 16) * strB + kb + aKof);
            LDSM4(ah[mt][0], ah[mt][1], ah[mt][2], ah[mt][3], uAhi + ra);
            LDSM4(al[mt][0], al[mt][1], al[mt][2], al[mt][3], uAlo + ra);
        }
#pragma unroll
        for (int np = 0; np < 2; np++) {
            const uint32_t rb = (uint32_t)((bRow + np * 16) * strB + kb + bKof);
            uint32_t t0, t1, t2, t3;
            LDSM4(t0, t1, t2, t3, uWhi + rb);
            bh[np * 2][0] = t0; bh[np * 2][1] = t1;
            bh[np * 2 + 1][0] = t2; bh[np * 2 + 1][1] = t3;
            LDSM4(t0, t1, t2, t3, uWlo + rb);
            bl[np * 2][0] = t0; bl[np * 2][1] = t1;
            bl[np * 2 + 1][0] = t2; bl[np * 2 + 1][1] = t3;
        }
#pragma unroll
        for (int mt = 0; mt < 2; mt++)
#pragma unroll
            for (int nt = 0; nt < 4; nt++) {
                MMA16816(acc[mt][nt], ah[mt], bh[nt][0], bh[nt][1]);
                MMA16816(acc[mt][nt], ah[mt], bl[nt][0], bl[nt][1]);
                MMA16816(acc[mt][nt], al[mt], bh[nt][0], bh[nt][1]);
            }
    }

#pragma unroll
    for (int mt = 0; mt < 2; mt++)
#pragma unroll
        for (int nt = 0; nt < 4; nt++) {
            const int row = m0 + mw * 32 + mt * 16 + (lane >> 2);
            const int col = n0 + nw * 32 + nt * 8 + (lane & 3) * 2;
            const float b0 = bias[col], b1 = bias[col + 1];
            float2 o0, o1;
            o0.x = acc[mt][nt][0] + b0; o0.y = acc[mt][nt][1] + b1;
            o1.x = acc[mt][nt][2] + b0; o1.y = acc[mt][nt][3] + b1;
            *(float2*)&C[(size_t)row * G_ + col]       = o0;
            *(float2*)&C[(size_t)(row + 8) * G_ + col] = o1;
        }
}

// ---------------- persistent GRU scan, HMMA + W-fragments-in-registers -------------
// R9 structure verbatim; single change: step-invariant Whh ldmatrix fragments are
// loaded ONCE into registers before the t-loop (96 regs/thread), halving hot-loop
// smem read traffic (16 LDSM + 72 HMMA per warp per step).
__global__ void __launch_bounds__(256, 1) gru_scan_mma(
    const float* __restrict__ gi, const float* __restrict__ Whh,
    const float* __restrict__ bhh,
    __nv_bfloat16* __restrict__ seqhi, __nv_bfloat16* __restrict__ seqlo, int tmajor)
{
    extern __shared__ char smc[];
    char* swhi_c = smc;                  // [24][528]  = 12672
    char* swlo_c = smc + 12672;          // 12672
    char* shhi_c = smc + 25344;          // [64][528]  = 33792
    char* shlo_c = smc + 59136;          // 33792
    float* part  = (float*)(smc + 92928);   // [2][64][25] = 12800 B
    float* gis   = (float*)(smc + 105728);  // [2][64*25]  = 12800 B
    float* hst   = (float*)(smc + 118528);  // [64][9]     = 2304 B
    float* bsl   = (float*)(smc + 120832);  // [24]
    __nv_bfloat16* swhi = (__nv_bfloat16*)swhi_c;
    __nv_bfloat16* swlo = (__nv_bfloat16*)swlo_c;

    const int tid = threadIdx.x;
    const int cta = blockIdx.x;
    const int bblk = cta >> 5;
    const int jblk = cta & 31;
    const int b0  = bblk * 64;
    const int j0  = jblk * 8;
    const int grp = bblk * 32;

    // ---- persistent Whh slice, split hi/lo ----
    for (int idx = tid; idx < 24 * 256; idx += 256) {
        const int row = idx >> 8, k = idx & 255;
        const float v = Whh[(size_t)((row >> 3) * H_ + j0 + (row & 7)) * H_ + k];
        const __nv_bfloat16 hi = __float2bfloat16(v);
        swhi[row * 264 + k] = hi;
        swlo[row * 264 + k] = __float2bfloat16(v - __bfloat162float(hi));
    }
    if (tid < 24) bsl[tid] = bhh[(tid >> 3) * H_ + j0 + (tid & 7)];
    for (int idx = tid; idx < 576; idx += 256) hst[idx] = 0.f;

    const int w = tid >> 5, lane = tid & 31;
    const int mt = w & 3, kh = w >> 2;

    // ldmatrix lane addressing (R8-validated)
    const int aoff   = (mt * 16 + (lane & 15)) * 528 + (lane >> 4) * 16;
    const int boff01 = ((lane & 7) + ((lane >> 4) << 3)) * 528 + ((lane >> 3) & 1) * 16;
    const int boff2  = (16 + (lane & 7)) * 528 + ((lane >> 3) & 1) * 16;
    const uint32_t uAhi = smem_u32(shhi_c), uAlo = smem_u32(shlo_c);
    const uint32_t uWhi = smem_u32(swhi_c), uWlo = smem_u32(swlo_c);
    __syncthreads();

    // ---- hoist step-invariant W fragments into registers (once for all 512 steps) --
    uint32_t wbh01[8][4], wbh2[8][2], wbl01[8][4], wbl2[8][2];
#pragma unroll
    for (int ks = 0; ks < 8; ks++) {
        const int kb = kh * 256 + ks * 32;
        LDSM4(wbh01[ks][0], wbh01[ks][1], wbh01[ks][2], wbh01[ks][3], uWhi + boff01 + kb);
        LDSM2(wbh2[ks][0], wbh2[ks][1], uWhi + boff2 + kb);
        LDSM4(wbl01[ks][0], wbl01[ks][1], wbl01[ks][2], wbl01[ks][3], uWlo + boff01 + kb);
        LDSM2(wbl2[ks][0], wbl2[ks][1], uWlo + boff2 + kb);
    }

    // per-thread gi staging map (6 elements), fixed across steps
    int gq_b[6], gq_sm[6], gq_col[6];
#pragma unroll
    for (int q = 0; q < 6; q++) {
        const int idx = tid + 256 * q;
        const int b = idx / 24, gg = idx % 24;
        gq_b[q] = b;
        gq_sm[q] = b * 25 + gg;
        gq_col[q] = (gg >> 3) * H_ + j0 + (gg & 7);
    }
    float greg[6];
#pragma unroll
    for (int q = 0; q < 6; q++) {
        const size_t row = tmajor ? ((size_t)0 * B_ + b0 + gq_b[q])
                                  : ((size_t)(b0 + gq_b[q]) * T_ + 0);
        greg[q] = gi[row * G_ + gq_col[q]];
    }
#pragma unroll
    for (int q = 0; q < 6; q++) gis[gq_sm[q]] = greg[q];
    __syncthreads();

    for (int t = 0; t < T_; t++) {
        const float* gcur = gis + (t & 1) * 1600;
        float* gnxt = gis + ((t + 1) & 1) * 1600;
        const int cur = t & 1, nxt = cur ^ 1;

        // ---- stage h_prev hi/lo (uint4, coalesced LDG / conflict-free STS) ----
        if (t == 0) {
            const uint4 z4 = make_uint4(0u, 0u, 0u, 0u);
#pragma unroll
            for (int q = 0; q < 8; q++) {
                const int v = tid + 256 * q;
                const int b = v >> 5, c = v & 31;
                *(uint4*)(shhi_c + b * 528 + c * 16) = z4;
                *(uint4*)(shlo_c + b * 528 + c * 16) = z4;
            }
        } else {
#pragma unroll
            for (int q = 0; q < 8; q++) {
                const int v = tid + 256 * q;
                const int b = v >> 5, c = v & 31;
                *(uint4*)(shhi_c + b * 528 + c * 16) =
                    *(const uint4*)&g_hbhi[cur][(b0 + b) * H_ + c * 8];
                *(uint4*)(shlo_c + b * 528 + c * 16) =
                    *(const uint4*)&g_hblo[cur][(b0 + b) * H_ + c * 8];
            }
        }

        // ---- prefetch gi(t+1) into registers (hidden under GEMM) ----
        {
            const int tn = (t + 1 < T_) ? (t + 1) : t;
#pragma unroll
            for (int q = 0; q < 6; q++) {
                const size_t row = tmajor ? ((size_t)tn * B_ + b0 + gq_b[q])
                                          : ((size_t)(b0 + gq_b[q]) * T_ + tn);
                greg[q] = __ldg(&gi[row * G_ + gq_col[q]]);
            }
        }
        __syncthreads();

        // ---- HMMA partial GEMM: 16 LDSM + 72 MMA per warp (W from registers) ----
        float a0[4] = {0.f, 0.f, 0.f, 0.f};
        float a1[4] = {0.f, 0.f, 0.f, 0.f};
        float a2[4] = {0.f, 0.f, 0.f, 0.f};
#pragma unroll
        for (int ks = 0; ks < 8; ks++) {
            const int kb = kh * 256 + ks * 32;
            uint32_t ah[4], al[4];
            LDSM4(ah[0], ah[1], ah[2], ah[3], uAhi + aoff + kb);
            LDSM4(al[0], al[1], al[2], al[3], uAlo + aoff + kb);
            MMA16816(a0, ah, wbh01[ks][0], wbh01[ks][1]);
            MMA16816(a1, ah, wbh01[ks][2], wbh01[ks][3]);
            MMA16816(a2, ah, wbh2[ks][0], wbh2[ks][1]);
            MMA16816(a0, ah, wbl01[ks][0], wbl01[ks][1]);
            MMA16816(a1, ah, wbl01[ks][2], wbl01[ks][3]);
            MMA16816(a2, ah, wbl2[ks][0], wbl2[ks][1]);
            MMA16816(a0, al, wbh01[ks][0], wbh01[ks][1]);
            MMA16816(a1, al, wbh01[ks][2], wbh01[ks][3]);
            MMA16816(a2, al, wbh2[ks][0], wbh2[ks][1]);
        }
        // store partials: fragment (row t/4 {+8}, col 2(t%4)+{0,1})
        {
            float* p = &part[(kh * 64 + mt * 16 + (lane >> 2)) * 25];
            const int col = 2 * (lane & 3);
            p[col] = a0[0];      p[col + 1] = a0[1];
            p[8 + col] = a1[0];  p[9 + col] = a1[1];
            p[16 + col] = a2[0]; p[17 + col] = a2[1];
            float* p8 = p + 8 * 25;
            p8[col] = a0[2];      p8[col + 1] = a0[3];
            p8[8 + col] = a1[2];  p8[9 + col] = a1[3];
            p8[16 + col] = a2[2]; p8[17 + col] = a2[3];
        }
#pragma unroll
        for (int q = 0; q < 6; q++) gnxt[gq_sm[q]] = greg[q];
        __syncthreads();

        // ---- reduce 2 partials + gate math (2 (b,jj) per thread) ----
        float vnew[2];
        int vb[2], vj[2];
#pragma unroll
        for (int p = 0; p < 2; p++) {
            const int pr = tid + p * 256;
            const int b = pr & 63, jj = pr >> 6;
            vb[p] = b; vj[p] = jj;
            const float* p0 = &part[b * 25];
            const float* p1 = &part[(64 + b) * 25];
            const float sr = bsl[jj] + p0[jj] + p1[jj] + gcur[b * 25 + jj];
            const float sz = bsl[8 + jj] + p0[8 + jj] + p1[8 + jj] + gcur[b * 25 + 8 + jj];
            const float sn = bsl[16 + jj] + p0[16 + jj] + p1[16 + jj];
            const float r = __fdividef(1.f, 1.f + __expf(-sr));
            const float z = __fdividef(1.f, 1.f + __expf(-sz));
            const float a = gcur[b * 25 + 16 + jj] + r * sn;
            const float n = __fdividef(2.f, 1.f + __expf(-2.f * a)) - 1.f;
            const float hold = hst[b * 9 + jj];
            vnew[p] = (1.f - z) * n + z * hold;
        }
        __syncthreads();
#pragma unroll
        for (int p = 0; p < 2; p++) hst[vb[p] * 9 + vj[p]] = vnew[p];
        __syncthreads();

        // ---- convert own slice to hi/lo and publish (threads 0..63) ----
        if (tid < 64) {
            const int b = tid;
            union { __nv_bfloat16 a8[8]; uint4 u; } uhi, ulo;
            float f[8];
#pragma unroll
            for (int j = 0; j < 8; j++) {
                f[j] = hst[b * 9 + j];
                uhi.a8[j] = __float2bfloat16(f[j]);
                ulo.a8[j] = __float2bfloat16(f[j] - __bfloat162float(uhi.a8[j]));
            }
            const size_t go = (size_t)(b0 + b) * H_ + j0;
            *(uint4*)&g_hbhi[nxt][go] = uhi.u;
            *(uint4*)&g_hblo[nxt][go] = ulo.u;
            if (seqhi) {
                const size_t so = ((size_t)t * B_ + b0 + b) * H_ + j0;
                *(uint4*)&seqhi[so] = uhi.u;
                *(uint4*)&seqlo[so] = ulo.u;
            }
            if (t == T_ - 1) {
                *(float4*)&g_hlast[go]     = make_float4(f[0], f[1], f[2], f[3]);
                *(float4*)&g_hlast[go + 4] = make_float4(f[4], f[5], f[6], f[7]);
            }
        }

        // ---- per-group (32 CTA) barrier (R4/R9-proven) ----
        __threadfence();
        __syncthreads();
        if (tid == 0) {
            const unsigned g = g_gen[grp];
            if (atomicAdd(&g_cnt[grp], 1u) == (unsigned)(GRP_CTAS - 1)) {
                g_cnt[grp] = 0;
                __threadfence();
                g_gen[grp] = g + 1u;
            } else {
                while (g_gen[grp] == g) {}
            }
            __threadfence();
        }
        __syncthreads();
    }
}

// ---------------- final FC: out[256,10] = h @ Wfc^T + bfc -------------------------
__global__ void fc_kernel(const float* __restrict__ h, const float* __restrict__ Wfc,
                          const float* __restrict__ bfc, float* __restrict__ out)
{
    const int b = blockIdx.x;
    const int lane = threadIdx.x;
    float hv[8];
#pragma unroll
    for (int i = 0; i < 8; i++) hv[i] = h[b * H_ + lane + 32 * i];
    for (int cc = 0; cc < C_; cc++) {
        float s = 0.f;
#pragma unroll
        for (int i = 0; i < 8; i++) s += hv[i] * Wfc[cc * H_ + lane + 32 * i];
#pragma unroll
        for (int o = 16; o > 0; o >>= 1) s += __shfl_down_sync(0xffffffffu, s, o);
        if (lane == 0) out[b * C_ + cc] = s + bfc[cc];
    }
}

// ---------------- launch ----------------------------------------------------------
extern "C" void kernel_launch(void* const* d_in, const int* in_sizes, int n_in,
                              void* d_out, int out_size)
{
    (void)in_sizes; (void)n_in; (void)out_size;
    const float* x    = (const float*)d_in[0];
    const float* Wih0 = (const float*)d_in[1];
    const float* Whh0 = (const float*)d_in[2];
    const float* bih0 = (const float*)d_in[3];
    const float* bhh0 = (const float*)d_in[4];
    const float* Wih1 = (const float*)d_in[5];
    const float* Whh1 = (const float*)d_in[6];
    const float* bih1 = (const float*)d_in[7];
    const float* bhh1 = (const float*)d_in[8];
    const float* Wfc  = (const float*)d_in[9];
    const float* bfc  = (const float*)d_in[10];
    float* out = (float*)d_out;

    float *p_gi, *p_hl;
    __nv_bfloat16 *p_ahi, *p_alo, *p_whi, *p_wlo, *p_shi, *p_slo;
    cudaGetSymbolAddress((void**)&p_gi, g_gi);
    cudaGetSymbolAddress((void**)&p_hl, g_hlast);
    cudaGetSymbolAddress((void**)&p_ahi, g_ahi);
    cudaGetSymbolAddress((void**)&p_alo, g_alo);
    cudaGetSymbolAddress((void**)&p_whi, g_whi);
    cudaGetSymbolAddress((void**)&p_wlo, g_wlo);
    cudaGetSymbolAddress((void**)&p_shi, g_seqhi);
    cudaGetSymbolAddress((void**)&p_slo, g_seqlo);

    const int scan_smem = 120928;
    cudaFuncSetAttribute(gru_scan_mma, cudaFuncAttributeMaxDynamicSharedMemorySize, scan_smem);
    const int gemm_smem1 = 384 * (256 + 8) * 2;
    const int gemm_smem0 = 384 * (128 + 8) * 2;
    cudaFuncSetAttribute(mma_gemm, cudaFuncAttributeMaxDynamicSharedMemorySize, gemm_smem1);

    const dim3 gtile(12, 1024);

    // ---- layer 0: gi0 = x @ Wih0^T + bih0 (rows b*T+t) ----
    split_bf16<<<(131072 * 128 / 4 + 255) / 256, 256>>>(x, p_ahi, p_alo, 131072 * 128 / 4);
    split_bf16<<<(G_ * D_ / 4 + 255) / 256, 256>>>(Wih0, p_whi, p_wlo, G_ * D_ / 4);
    mma_gemm<<<gtile, 256, gemm_smem0>>>(p_ahi, p_alo, p_whi, p_wlo, bih0, p_gi, D_);
    gru_scan_mma<<<NCTA_SCAN, 256, scan_smem>>>(p_gi, Whh0, bhh0, p_shi, p_slo, /*tmajor=*/0);

    // ---- layer 1: gi1 = h1 @ Wih1^T + bih1 (rows t*B+b, hi/lo straight from scan) ----
    split_bf16<<<(G_ * H_ / 4 + 255) / 256, 256>>>(Wih1, p_whi, p_wlo, G_ * H_ / 4);
    mma_gemm<<<gtile, 256, gemm_smem1>>>(p_shi, p_slo, p_whi, p_wlo, bih1, p_gi, H_);
    gru_scan_mma<<<NCTA_SCAN, 256, scan_smem>>>(p_gi, Whh1, bhh1, nullptr, nullptr, /*tmajor=*/1);

    // classifier on final hidden state
    fc_kernel<<<B_, 32>>>(p_hl, Wfc, bfc, out);
}

// round 13
// speedup vs baseline: 1.7741x; 1.2210x over previous
#include <cuda_runtime.h>
#include <cuda_bf16.h>
#include <math.h>
#include <stdint.h>

#define B_  256
#define T_  512
#define D_  128
#define H_  256
#define G_  768
#define C_  10

// ---------------- warp-mma helpers (sm_80+ baseline; compiles for plain sm_103) ---
__device__ __forceinline__ uint32_t smem_u32(const void* p) {
    uint32_t a;
    asm("{ .reg .u64 t; cvta.to.shared.u64 t, %1; cvt.u32.u64 %0, t; }" : "=r"(a) : "l"(p));
    return a;
}
#define LDSM4(r0, r1, r2, r3, addr) \
    asm volatile("ldmatrix.sync.aligned.m8n8.x4.shared.b16 {%0,%1,%2,%3}, [%4];" \
        : "=r"(r0), "=r"(r1), "=r"(r2), "=r"(r3) : "r"(addr))
#define MMA16816(c, a, b0v, b1v) \
    asm volatile("mma.sync.aligned.m16n8k16.row.col.f32.bf16.bf16.f32 " \
        "{%0,%1,%2,%3},{%4,%5,%6,%7},{%8,%9},{%0,%1,%2,%3};" \
        : "+f"((c)[0]), "+f"((c)[1]), "+f"((c)[2]), "+f"((c)[3]) \
        : "r"((a)[0]), "r"((a)[1]), "r"((a)[2]), "r"((a)[3]), "r"(b0v), "r"(b1v))

// ---------------- scratch (device globals; no allocation allowed) ----------------
__device__ float g_gi[(size_t)B_ * T_ * G_];            // gi for layer 0
__device__ __nv_bfloat16 g_seqhi[(size_t)T_ * B_ * H_]; // layer-0 h sequence, bf16 hi
__device__ __nv_bfloat16 g_seqlo[(size_t)T_ * B_ * H_]; // layer-0 h sequence, bf16 lo
__device__ __nv_bfloat16 g_hbhi[2][B_ * H_];            // layer-1 h ping-pong (hi)
__device__ __nv_bfloat16 g_hblo[2][B_ * H_];            // layer-1 h ping-pong (lo)
__device__ float g_hlast[B_ * H_];                      // final fp32 h2 for the FC
__device__ volatile unsigned g_gen0[4 * 32];            // layer-0 group generation
__device__ unsigned g_cnt0[4 * 32];
__device__ volatile unsigned g_gen1[4 * 32];            // layer-1 group generation
__device__ unsigned g_cnt1[4 * 32];
__device__ __nv_bfloat16 g_ahi[(size_t)131072 * 128];   // x split
__device__ __nv_bfloat16 g_alo[(size_t)131072 * 128];
__device__ __nv_bfloat16 g_whi[G_ * D_];                // Wih0 split
__device__ __nv_bfloat16 g_wlo[G_ * D_];

// ---------------- reset barrier state (graph-replay safe) --------------------------
__global__ void reset_bar()
{
    const int i = threadIdx.x;
    if (i < 128) {
        g_cnt0[i] = 0u; ((unsigned*)g_gen0)[i] = 0u;
        g_cnt1[i] = 0u; ((unsigned*)g_gen1)[i] = 0u;
    }
}

// ---------------- fp32 -> (bf16 hi, bf16 lo) split ---------------------------------
__global__ void split_bf16(const float* __restrict__ s, __nv_bfloat16* __restrict__ hi,
                           __nv_bfloat16* __restrict__ lo, int n4)
{
    const int i = blockIdx.x * blockDim.x + threadIdx.x;
    if (i >= n4) return;
    const float4 v = ((const float4*)s)[i];
    __nv_bfloat16 h0 = __float2bfloat16(v.x);
    __nv_bfloat16 h1 = __float2bfloat16(v.y);
    __nv_bfloat16 h2 = __float2bfloat16(v.z);
    __nv_bfloat16 h3 = __float2bfloat16(v.w);
    __nv_bfloat16 l0 = __float2bfloat16(v.x - __bfloat162float(h0));
    __nv_bfloat16 l1 = __float2bfloat16(v.y - __bfloat162float(h1));
    __nv_bfloat16 l2 = __float2bfloat16(v.z - __bfloat162float(h2));
    __nv_bfloat16 l3 = __float2bfloat16(v.w - __bfloat162float(h3));
    __nv_bfloat162* hp = (__nv_bfloat162*)hi;
    __nv_bfloat162* lp = (__nv_bfloat162*)lo;
    hp[i * 2 + 0] = __nv_bfloat162(h0, h1);
    hp[i * 2 + 1] = __nv_bfloat162(h2, h3);
    lp[i * 2 + 0] = __nv_bfloat162(l0, l1);
    lp[i * 2 + 1] = __nv_bfloat162(l2, l3);
}

// ---------------- split-bf16 HMMA GEMM (R8-proven; layer-0 gi only, K=128) ---------
__global__ void __launch_bounds__(256, 1) mma_gemm(
    const __nv_bfloat16* __restrict__ Ahi, const __nv_bfloat16* __restrict__ Alo,
    const __nv_bfloat16* __restrict__ Whi, const __nv_bfloat16* __restrict__ Wlo,
    const float* __restrict__ bias, float* __restrict__ C, int K)
{
    extern __shared__ char smem[];
    const int KS = K + 8;
    const int strB = KS * 2;
    char* sAhi = smem;
    char* sAlo = sAhi + 128 * strB;
    char* sWhi = sAlo + 128 * strB;
    char* sWlo = sWhi + 64 * strB;

    const int tid = threadIdx.x;
    const int n0 = blockIdx.x * 64;
    const int m0 = blockIdx.y * 128;

    const int cpr = K >> 3;
    for (int c = tid; c < 128 * cpr; c += 256) {
        const int r = c / cpr, kc = c % cpr;
        const size_t src = (size_t)(m0 + r) * K + kc * 8;
        *(uint4*)(sAhi + r * strB + kc * 16) = *(const uint4*)(Ahi + src);
        *(uint4*)(sAlo + r * strB + kc * 16) = *(const uint4*)(Alo + src);
    }
    for (int c = tid; c < 64 * cpr; c += 256) {
        const int r = c / cpr, kc = c % cpr;
        const size_t src = (size_t)(n0 + r) * K + kc * 8;
        *(uint4*)(sWhi + r * strB + kc * 16) = *(const uint4*)(Whi + src);
        *(uint4*)(sWlo + r * strB + kc * 16) = *(const uint4*)(Wlo + src);
    }
    __syncthreads();

    const int wid = tid >> 5, lane = tid & 31;
    const int mw = wid >> 1, nw = wid & 1;

    float acc[2][4][4];
#pragma unroll
    for (int mt = 0; mt < 2; mt++)
#pragma unroll
        for (int nt = 0; nt < 4; nt++)
#pragma unroll
            for (int q = 0; q < 4; q++) acc[mt][nt][q] = 0.f;

    const int aRow = mw * 32 + (lane & 15);
    const int aKof = (lane >> 4) * 16;
    const int bRow = nw * 32 + (lane & 7) + ((lane >> 4) << 3);
    const int bKof = ((lane >> 3) & 1) * 16;

    const uint32_t uAhi = smem_u32(sAhi), uAlo = smem_u32(sAlo);
    const uint32_t uWhi = smem_u32(sWhi), uWlo = smem_u32(sWlo);

    const int nks = K >> 4;
    for (int ks = 0; ks < nks; ks++) {
        const int kb = ks * 32;
        uint32_t ah[2][4], al[2][4], bh[4][2], bl[4][2];
#pragma unroll
        for (int mt = 0; mt < 2; mt++) {
            const uint32_t ra = (uint32_t)((aRow + mt * 16) * strB + kb + aKof);
            LDSM4(ah[mt][0], ah[mt][1], ah[mt][2], ah[mt][3], uAhi + ra);
            LDSM4(al[mt][0], al[mt][1], al[mt][2], al[mt][3], uAlo + ra);
        }
#pragma unroll
        for (int np = 0; np < 2; np++) {
            const uint32_t rb = (uint32_t)((bRow + np * 16) * strB + kb + bKof);
            uint32_t t0, t1, t2, t3;
            LDSM4(t0, t1, t2, t3, uWhi + rb);
            bh[np * 2][0] = t0; bh[np * 2][1] = t1;
            bh[np * 2 + 1][0] = t2; bh[np * 2 + 1][1] = t3;
            LDSM4(t0, t1, t2, t3, uWlo + rb);
            bl[np * 2][0] = t0; bl[np * 2][1] = t1;
            bl[np * 2 + 1][0] = t2; bl[np * 2 + 1][1] = t3;
        }
#pragma unroll
        for (int mt = 0; mt < 2; mt++)
#pragma unroll
            for (int nt = 0; nt < 4; nt++) {
                MMA16816(acc[mt][nt], ah[mt], bh[nt][0], bh[nt][1]);
                MMA16816(acc[mt][nt], ah[mt], bl[nt][0], bl[nt][1]);
                MMA16816(acc[mt][nt], al[mt], bh[nt][0], bh[nt][1]);
            }
    }

#pragma unroll
    for (int mt = 0; mt < 2; mt++)
#pragma unroll
        for (int nt = 0; nt < 4; nt++) {
            const int row = m0 + mw * 32 + mt * 16 + (lane >> 2);
            const int col = n0 + nw * 32 + nt * 8 + (lane & 3) * 2;
            const float b0 = bias[col], b1 = bias[col + 1];
            float2 o0, o1;
            o0.x = acc[mt][nt][0] + b0; o0.y = acc[mt][nt][1] + b1;
            o1.x = acc[mt][nt][2] + b0; o1.y = acc[mt][nt][3] + b1;
            *(float2*)&C[(size_t)row * G_ + col]       = o0;
            *(float2*)&C[(size_t)(row + 8) * G_ + col] = o1;
        }
}

// ---------------- fused two-layer GRU scan ------------------------------------------
// 128 CTAs x 256 threads. CTA<64: layer 0; CTA>=64: layer 1 (lags one step).
// Per-layer partition: 4 batch-groups x 16 jblk; CTA = 64 batches x 16 hidden dims
// (48 gate rows). Layer-0 consumes precomputed gi0, publishes h1 as bf16 hi/lo into
// the seq buffers. Layer-1 stages h1(t) from seq, computes gi1 on the fly (HMMA GEMM
// vs smem-resident Wih1 slice), plus its recurrent GEMM vs Whh1, gates, ping-pong h2.
// Sync: layer-0 16-CTA group barrier (gen0); layer-1 waits gen0>=t+1 + own gen1.
__global__ void __launch_bounds__(256, 1) gru_fused(
    const float* __restrict__ gi0, const float* __restrict__ Whh0,
    const float* __restrict__ bhh0,
    const float* __restrict__ Wih1, const float* __restrict__ bih1,
    const float* __restrict__ Whh1, const float* __restrict__ bhh1)
{
    extern __shared__ char smc[];
    const int tid = threadIdx.x;
    const int cta = blockIdx.x;
    const int layer = cta >> 6;
    const int lid = cta & 63;
    const int bblk = lid >> 4, jblk = lid & 15;
    const int b0 = bblk * 64, j0 = jblk * 16;
    const int slot = bblk * 32;

    const int w = tid >> 5, lane = tid & 31;
    const int mt = w & 3, kh = w >> 2;
    const int aoff = (mt * 16 + (lane & 15)) * 528 + (lane >> 4) * 16;
    const int brow = (lane & 7) + ((lane >> 4) << 3);
    const int bko  = ((lane >> 3) & 1) * 16;

    if (layer == 0) {
        // smem: swhh hi 0/25344, lo 25344; sh hi 50688, lo 84480;
        //       part 118272/25088; gis 143360/25088; hst 168448/4352; bsl 172800/192
        __nv_bfloat16* swhi = (__nv_bfloat16*)smc;
        __nv_bfloat16* swlo = (__nv_bfloat16*)(smc + 25344);
        char* shhi = smc + 50688;
        char* shlo = smc + 84480;
        float* part = (float*)(smc + 118272);
        float* gis  = (float*)(smc + 143360);
        float* hst  = (float*)(smc + 168448);
        float* bsl  = (float*)(smc + 172800);

        for (int idx = tid; idx < 48 * 256; idx += 256) {
            const int row = idx >> 8, k = idx & 255;
            const float v = Whh0[(size_t)((row >> 4) * H_ + j0 + (row & 15)) * H_ + k];
            const __nv_bfloat16 hi = __float2bfloat16(v);
            swhi[row * 264 + k] = hi;
            swlo[row * 264 + k] = __float2bfloat16(v - __bfloat162float(hi));
        }
        if (tid < 48) bsl[tid] = bhh0[(tid >> 4) * H_ + j0 + (tid & 15)];
        for (int idx = tid; idx < 64 * 17; idx += 256) hst[idx] = 0.f;

        const uint32_t uAhi = smem_u32(shhi), uAlo = smem_u32(shlo);
        const uint32_t uWhi = smem_u32(smc), uWlo = smem_u32(smc + 25344);

        int gq_b[12], gq_sm[12], gq_col[12];
#pragma unroll
        for (int q = 0; q < 12; q++) {
            const int idx = tid + 256 * q;
            const int b = idx / 48, gg = idx % 48;
            gq_b[q] = b;
            gq_sm[q] = b * 49 + gg;
            gq_col[q] = (gg >> 4) * H_ + j0 + (gg & 15);
        }
        float greg[12];
#pragma unroll
        for (int q = 0; q < 12; q++)
            greg[q] = gi0[((size_t)(b0 + gq_b[q]) * T_ + 0) * G_ + gq_col[q]];
#pragma unroll
        for (int q = 0; q < 12; q++) gis[gq_sm[q]] = greg[q];
        __syncthreads();

        for (int t = 0; t < T_; t++) {
            const float* gcur = gis + (t & 1) * 3136;
            float* gnxt = gis + ((t + 1) & 1) * 3136;

            if (t == 0) {
                const uint4 z4 = make_uint4(0u, 0u, 0u, 0u);
#pragma unroll
                for (int q = 0; q < 8; q++) {
                    const int v = tid + 256 * q;
                    const int b = v >> 5, c = v & 31;
                    *(uint4*)(shhi + b * 528 + c * 16) = z4;
                    *(uint4*)(shlo + b * 528 + c * 16) = z4;
                }
            } else {
#pragma unroll
                for (int q = 0; q < 8; q++) {
                    const int v = tid + 256 * q;
                    const int b = v >> 5, c = v & 31;
                    const size_t so = ((size_t)(t - 1) * B_ + b0 + b) * H_ + c * 8;
                    *(uint4*)(shhi + b * 528 + c * 16) = *(const uint4*)&g_seqhi[so];
                    *(uint4*)(shlo + b * 528 + c * 16) = *(const uint4*)&g_seqlo[so];
                }
            }
            {
                const int tn = (t + 1 < T_) ? (t + 1) : t;
#pragma unroll
                for (int q = 0; q < 12; q++)
                    greg[q] = __ldg(&gi0[((size_t)(b0 + gq_b[q]) * T_ + tn) * G_ + gq_col[q]]);
            }
            __syncthreads();

            float acc[6][4];
#pragma unroll
            for (int nt = 0; nt < 6; nt++)
#pragma unroll
                for (int q = 0; q < 4; q++) acc[nt][q] = 0.f;
#pragma unroll
            for (int ks = 0; ks < 8; ks++) {
                const int kb = kh * 256 + ks * 32;
                uint32_t ah[4], al[4], bh[6][2], bl[6][2];
                LDSM4(ah[0], ah[1], ah[2], ah[3], uAhi + aoff + kb);
                LDSM4(al[0], al[1], al[2], al[3], uAlo + aoff + kb);
#pragma unroll
                for (int p = 0; p < 3; p++) {
                    const uint32_t rb = (uint32_t)((p * 16 + brow) * 528 + bko + kb);
                    uint32_t t0, t1, t2, t3;
                    LDSM4(t0, t1, t2, t3, uWhi + rb);
                    bh[p * 2][0] = t0; bh[p * 2][1] = t1;
                    bh[p * 2 + 1][0] = t2; bh[p * 2 + 1][1] = t3;
                    LDSM4(t0, t1, t2, t3, uWlo + rb);
                    bl[p * 2][0] = t0; bl[p * 2][1] = t1;
                    bl[p * 2 + 1][0] = t2; bl[p * 2 + 1][1] = t3;
                }
#pragma unroll
                for (int nt = 0; nt < 6; nt++) {
                    MMA16816(acc[nt], ah, bh[nt][0], bh[nt][1]);
                    MMA16816(acc[nt], ah, bl[nt][0], bl[nt][1]);
                    MMA16816(acc[nt], al, bh[nt][0], bh[nt][1]);
                }
            }
            {
                float* pp = &part[(kh * 64 + mt * 16 + (lane >> 2)) * 49];
                float* p8 = pp + 8 * 49;
                const int c2 = 2 * (lane & 3);
#pragma unroll
                for (int nt = 0; nt < 6; nt++) {
                    pp[nt * 8 + c2] = acc[nt][0]; pp[nt * 8 + c2 + 1] = acc[nt][1];
                    p8[nt * 8 + c2] = acc[nt][2]; p8[nt * 8 + c2 + 1] = acc[nt][3];
                }
            }
#pragma unroll
            for (int q = 0; q < 12; q++) gnxt[gq_sm[q]] = greg[q];
            __syncthreads();

            float vnew[4];
            int vb[4], vj[4];
#pragma unroll
            for (int p = 0; p < 4; p++) {
                const int pr = tid + p * 256;
                const int b = pr & 63, jj = pr >> 6;
                vb[p] = b; vj[p] = jj;
                const float* p0 = &part[b * 49];
                const float* p1 = &part[(64 + b) * 49];
                const float sr = bsl[jj] + p0[jj] + p1[jj] + gcur[b * 49 + jj];
                const float sz = bsl[16 + jj] + p0[16 + jj] + p1[16 + jj]
                               + gcur[b * 49 + 16 + jj];
                const float sn = bsl[32 + jj] + p0[32 + jj] + p1[32 + jj];
                const float r = __fdividef(1.f, 1.f + __expf(-sr));
                const float z = __fdividef(1.f, 1.f + __expf(-sz));
                const float a = gcur[b * 49 + 32 + jj] + r * sn;
                const float n = __fdividef(2.f, 1.f + __expf(-2.f * a)) - 1.f;
                vnew[p] = (1.f - z) * n + z * hst[b * 17 + jj];
            }
            __syncthreads();
#pragma unroll
            for (int p = 0; p < 4; p++) hst[vb[p] * 17 + vj[p]] = vnew[p];
            __syncthreads();

            if (tid < 128) {
                const int b = tid >> 1, seg = tid & 1;
                union { __nv_bfloat16 a8[8]; uint4 u; } uhi, ulo;
#pragma unroll
                for (int j = 0; j < 8; j++) {
                    const float f = hst[b * 17 + seg * 8 + j];
                    uhi.a8[j] = __float2bfloat16(f);
                    ulo.a8[j] = __float2bfloat16(f - __bfloat162float(uhi.a8[j]));
                }
                const size_t so = ((size_t)t * B_ + b0 + b) * H_ + j0 + seg * 8;
                *(uint4*)&g_seqhi[so] = uhi.u;
                *(uint4*)&g_seqlo[so] = ulo.u;
            }

            __threadfence();
            __syncthreads();
            if (tid == 0) {
                const unsigned a = atomicAdd(&g_cnt0[slot], 1u);
                if (a == 15u) {
                    g_cnt0[slot] = 0u;
                    __threadfence();
                    g_gen0[slot] = (unsigned)(t + 1);
                } else {
                    while (g_gen0[slot] < (unsigned)(t + 1)) {}
                }
                __threadfence();
            }
            __syncthreads();
        }
    } else {
        // smem: swih hi 0, lo 25344; swhh hi 50688, lo 76032; sh hi 101376, lo 135168;
        //       part 168960/25088; partN 194048/8704; hst 202752/4352;
        //       bih 207104/192; bhh 207296/192
        __nv_bfloat16* sih_h = (__nv_bfloat16*)smc;
        __nv_bfloat16* sih_l = (__nv_bfloat16*)(smc + 25344);
        __nv_bfloat16* shh_h = (__nv_bfloat16*)(smc + 50688);
        __nv_bfloat16* shh_l = (__nv_bfloat16*)(smc + 76032);
        char* shhi = smc + 101376;
        char* shlo = smc + 135168;
        float* part  = (float*)(smc + 168960);
        float* partN = (float*)(smc + 194048);
        float* hst   = (float*)(smc + 202752);
        float* bih   = (float*)(smc + 207104);
        float* bhh   = (float*)(smc + 207296);

        for (int idx = tid; idx < 48 * 256; idx += 256) {
            const int row = idx >> 8, k = idx & 255;
            const size_t wr = (size_t)((row >> 4) * H_ + j0 + (row & 15)) * H_ + k;
            {
                const float v = Wih1[wr];
                const __nv_bfloat16 hi = __float2bfloat16(v);
                sih_h[row * 264 + k] = hi;
                sih_l[row * 264 + k] = __float2bfloat16(v - __bfloat162float(hi));
            }
            {
                const float v = Whh1[wr];
                const __nv_bfloat16 hi = __float2bfloat16(v);
                shh_h[row * 264 + k] = hi;
                shh_l[row * 264 + k] = __float2bfloat16(v - __bfloat162float(hi));
            }
        }
        if (tid < 48) {
            bih[tid] = bih1[(tid >> 4) * H_ + j0 + (tid & 15)];
            bhh[tid] = bhh1[(tid >> 4) * H_ + j0 + (tid & 15)];
        }
        for (int idx = tid; idx < 64 * 17; idx += 256) hst[idx] = 0.f;

        const uint32_t uAhi = smem_u32(shhi), uAlo = smem_u32(shlo);
        const uint32_t uIhi = smem_u32(smc), uIlo = smem_u32(smc + 25344);
        const uint32_t uHhi = smem_u32(smc + 50688), uHlo = smem_u32(smc + 76032);
        __syncthreads();

        for (int t = 0; t < T_; t++) {
            const int cur = t & 1, nxt = cur ^ 1;

            // wait for layer-0 to have produced h1(t)
            if (tid == 0) {
                while (g_gen0[slot] < (unsigned)(t + 1)) {}
                __threadfence();
            }
            __syncthreads();

            // ---- phase A: stage h1(t) from seq, GEMM vs Wih1 ----
#pragma unroll
            for (int q = 0; q < 8; q++) {
                const int v = tid + 256 * q;
                const int b = v >> 5, c = v & 31;
                const size_t so = ((size_t)t * B_ + b0 + b) * H_ + c * 8;
                *(uint4*)(shhi + b * 528 + c * 16) = *(const uint4*)&g_seqhi[so];
                *(uint4*)(shlo + b * 528 + c * 16) = *(const uint4*)&g_seqlo[so];
            }
            __syncthreads();

            float acc[6][4], accN[2][4];
#pragma unroll
            for (int nt = 0; nt < 6; nt++)
#pragma unroll
                for (int q = 0; q < 4; q++) acc[nt][q] = 0.f;
#pragma unroll
            for (int nt = 0; nt < 2; nt++)
#pragma unroll
                for (int q = 0; q < 4; q++) accN[nt][q] = 0.f;

#pragma unroll
            for (int ks = 0; ks < 8; ks++) {
                const int kb = kh * 256 + ks * 32;
                uint32_t ah[4], al[4], bh[6][2], bl[6][2];
                LDSM4(ah[0], ah[1], ah[2], ah[3], uAhi + aoff + kb);
                LDSM4(al[0], al[1], al[2], al[3], uAlo + aoff + kb);
#pragma unroll
                for (int p = 0; p < 3; p++) {
                    const uint32_t rb = (uint32_t)((p * 16 + brow) * 528 + bko + kb);
                    uint32_t t0, t1, t2, t3;
                    LDSM4(t0, t1, t2, t3, uIhi + rb);
                    bh[p * 2][0] = t0; bh[p * 2][1] = t1;
                    bh[p * 2 + 1][0] = t2; bh[p * 2 + 1][1] = t3;
                    LDSM4(t0, t1, t2, t3, uIlo + rb);
                    bl[p * 2][0] = t0; bl[p * 2][1] = t1;
                    bl[p * 2 + 1][0] = t2; bl[p * 2 + 1][1] = t3;
                }
#pragma unroll
                for (int nt = 0; nt < 6; nt++) {
                    MMA16816(acc[nt], ah, bh[nt][0], bh[nt][1]);
                    MMA16816(acc[nt], ah, bl[nt][0], bl[nt][1]);
                    MMA16816(acc[nt], al, bh[nt][0], bh[nt][1]);
                }
            }
            __syncthreads();   // before restaging the shared h buffer

            // ---- phase B: stage h2(t-1), GEMM vs Whh1 (n-tiles to accN) ----
            if (t == 0) {
                const uint4 z4 = make_uint4(0u, 0u, 0u, 0u);
#pragma unroll
                for (int q = 0; q < 8; q++) {
                    const int v = tid + 256 * q;
                    const int b = v >> 5, c = v & 31;
                    *(uint4*)(shhi + b * 528 + c * 16) = z4;
                    *(uint4*)(shlo + b * 528 + c * 16) = z4;
                }
            } else {
#pragma unroll
                for (int q = 0; q < 8; q++) {
                    const int v = tid + 256 * q;
                    const int b = v >> 5, c = v & 31;
                    *(uint4*)(shhi + b * 528 + c * 16) =
                        *(const uint4*)&g_hbhi[cur][(b0 + b) * H_ + c * 8];
                    *(uint4*)(shlo + b * 528 + c * 16) =
                        *(const uint4*)&g_hblo[cur][(b0 + b) * H_ + c * 8];
                }
            }
            __syncthreads();

#pragma unroll
            for (int ks = 0; ks < 8; ks++) {
                const int kb = kh * 256 + ks * 32;
                uint32_t ah[4], al[4], bh[6][2], bl[6][2];
                LDSM4(ah[0], ah[1], ah[2], ah[3], uAhi + aoff + kb);
                LDSM4(al[0], al[1], al[2], al[3], uAlo + aoff + kb);
#pragma unroll
                for (int p = 0; p < 3; p++) {
                    const uint32_t rb = (uint32_t)((p * 16 + brow) * 528 + bko + kb);
                    uint32_t t0, t1, t2, t3;
                    LDSM4(t0, t1, t2, t3, uHhi + rb);
                    bh[p * 2][0] = t0; bh[p * 2][1] = t1;
                    bh[p * 2 + 1][0] = t2; bh[p * 2 + 1][1] = t3;
                    LDSM4(t0, t1, t2, t3, uHlo + rb);
                    bl[p * 2][0] = t0; bl[p * 2][1] = t1;
                    bl[p * 2 + 1][0] = t2; bl[p * 2 + 1][1] = t3;
                }
#pragma unroll
                for (int nt = 0; nt < 4; nt++) {
                    MMA16816(acc[nt], ah, bh[nt][0], bh[nt][1]);
                    MMA16816(acc[nt], ah, bl[nt][0], bl[nt][1]);
                    MMA16816(acc[nt], al, bh[nt][0], bh[nt][1]);
                }
#pragma unroll
                for (int nt = 4; nt < 6; nt++) {
                    MMA16816(accN[nt - 4], ah, bh[nt][0], bh[nt][1]);
                    MMA16816(accN[nt - 4], ah, bl[nt][0], bl[nt][1]);
                    MMA16816(accN[nt - 4], al, bh[nt][0], bh[nt][1]);
                }
            }
            {
                const int prow = mt * 16 + (lane >> 2);
                float* pp = &part[(kh * 64 + prow) * 49];
                float* p8 = pp + 8 * 49;
                const int c2 = 2 * (lane & 3);
#pragma unroll
                for (int nt = 0; nt < 6; nt++) {
                    pp[nt * 8 + c2] = acc[nt][0]; pp[nt * 8 + c2 + 1] = acc[nt][1];
                    p8[nt * 8 + c2] = acc[nt][2]; p8[nt * 8 + c2 + 1] = acc[nt][3];
                }
                float* pn = &partN[kh * 1088 + prow * 17];
                float* pn8 = pn + 8 * 17;
#pragma unroll
                for (int nt = 0; nt < 2; nt++) {
                    pn[nt * 8 + c2] = accN[nt][0]; pn[nt * 8 + c2 + 1] = accN[nt][1];
                    pn8[nt * 8 + c2] = accN[nt][2]; pn8[nt * 8 + c2 + 1] = accN[nt][3];
                }
            }
            __syncthreads();

            // ---- gates: 4 (b,jj) per thread ----
            float vnew[4];
            int vb[4], vj[4];
#pragma unroll
            for (int p = 0; p < 4; p++) {
                const int pr = tid + p * 256;
                const int b = pr & 63, jj = pr >> 6;
                vb[p] = b; vj[p] = jj;
                const float* p0 = &part[b * 49];
                const float* p1 = &part[(64 + b) * 49];
                const float sr = bih[jj] + bhh[jj] + p0[jj] + p1[jj];
                const float sz = bih[16 + jj] + bhh[16 + jj]
                               + p0[16 + jj] + p1[16 + jj];
                const float gin = bih[32 + jj] + p0[32 + jj] + p1[32 + jj];
                const float ghn = bhh[32 + jj]
                                + partN[b * 17 + jj] + partN[1088 + b * 17 + jj];
                const float r = __fdividef(1.f, 1.f + __expf(-sr));
                const float z = __fdividef(1.f, 1.f + __expf(-sz));
                const float a = gin + r * ghn;
                const float n = __fdividef(2.f, 1.f + __expf(-2.f * a)) - 1.f;
                vnew[p] = (1.f - z) * n + z * hst[b * 17 + jj];
            }
            __syncthreads();
#pragma unroll
            for (int p = 0; p < 4; p++) hst[vb[p] * 17 + vj[p]] = vnew[p];
            __syncthreads();

            // ---- publish h2(t) ----
            if (tid < 128) {
                const int b = tid >> 1, seg = tid & 1;
                float f[8];
                union { __nv_bfloat16 a8[8]; uint4 u; } uhi, ulo;
#pragma unroll
                for (int j = 0; j < 8; j++) {
                    f[j] = hst[b * 17 + seg * 8 + j];
                    uhi.a8[j] = __float2bfloat16(f[j]);
                    ulo.a8[j] = __float2bfloat16(f[j] - __bfloat162float(uhi.a8[j]));
                }
                const size_t go = (size_t)(b0 + b) * H_ + j0 + seg * 8;
                *(uint4*)&g_hbhi[nxt][go] = uhi.u;
                *(uint4*)&g_hblo[nxt][go] = ulo.u;
                if (t == T_ - 1) {
                    *(float4*)&g_hlast[go]     = make_float4(f[0], f[1], f[2], f[3]);
                    *(float4*)&g_hlast[go + 4] = make_float4(f[4], f[5], f[6], f[7]);
                }
            }

            __threadfence();
            __syncthreads();
            if (tid == 0) {
                const unsigned a = atomicAdd(&g_cnt1[slot], 1u);
                if (a == 15u) {
                    g_cnt1[slot] = 0u;
                    __threadfence();
                    g_gen1[slot] = (unsigned)(t + 1);
                } else {
                    while (g_gen1[slot] < (unsigned)(t + 1)) {}
                }
                __threadfence();
            }
            __syncthreads();
        }
    }
}

// ---------------- final FC: out[256,10] = h @ Wfc^T + bfc -------------------------
__global__ void fc_kernel(const float* __restrict__ h, const float* __restrict__ Wfc,
                          const float* __restrict__ bfc, float* __restrict__ out)
{
    const int b = blockIdx.x;
    const int lane = threadIdx.x;
    float hv[8];
#pragma unroll
    for (int i = 0; i < 8; i++) hv[i] = h[b * H_ + lane + 32 * i];
    for (int cc = 0; cc < C_; cc++) {
        float s = 0.f;
#pragma unroll
        for (int i = 0; i < 8; i++) s += hv[i] * Wfc[cc * H_ + lane + 32 * i];
#pragma unroll
        for (int o = 16; o > 0; o >>= 1) s += __shfl_down_sync(0xffffffffu, s, o);
        if (lane == 0) out[b * C_ + cc] = s + bfc[cc];
    }
}

// ---------------- launch ----------------------------------------------------------
extern "C" void kernel_launch(void* const* d_in, const int* in_sizes, int n_in,
                              void* d_out, int out_size)
{
    (void)in_sizes; (void)n_in; (void)out_size;
    const float* x    = (const float*)d_in[0];
    const float* Wih0 = (const float*)d_in[1];
    const float* Whh0 = (const float*)d_in[2];
    const float* bih0 = (const float*)d_in[3];
    const float* bhh0 = (const float*)d_in[4];
    const float* Wih1 = (const float*)d_in[5];
    const float* Whh1 = (const float*)d_in[6];
    const float* bih1 = (const float*)d_in[7];
    const float* bhh1 = (const float*)d_in[8];
    const float* Wfc  = (const float*)d_in[9];
    const float* bfc  = (const float*)d_in[10];
    float* out = (float*)d_out;

    float *p_gi, *p_hl;
    __nv_bfloat16 *p_ahi, *p_alo, *p_whi, *p_wlo;
    cudaGetSymbolAddress((void**)&p_gi, g_gi);
    cudaGetSymbolAddress((void**)&p_hl, g_hlast);
    cudaGetSymbolAddress((void**)&p_ahi, g_ahi);
    cudaGetSymbolAddress((void**)&p_alo, g_alo);
    cudaGetSymbolAddress((void**)&p_whi, g_whi);
    cudaGetSymbolAddress((void**)&p_wlo, g_wlo);

    const int fused_smem = 207488;
    cudaFuncSetAttribute(gru_fused, cudaFuncAttributeMaxDynamicSharedMemorySize, fused_smem);
    const int gemm_smem0 = 384 * (128 + 8) * 2;
    cudaFuncSetAttribute(mma_gemm, cudaFuncAttributeMaxDynamicSharedMemorySize, gemm_smem0);

    // layer-0 gi GEMM: gi0 = x @ Wih0^T + bih0 (rows b*T+t)
    split_bf16<<<(131072 * 128 / 4 + 255) / 256, 256>>>(x, p_ahi, p_alo, 131072 * 128 / 4);
    split_bf16<<<(G_ * D_ / 4 + 255) / 256, 256>>>(Wih0, p_whi, p_wlo, G_ * D_ / 4);
    mma_gemm<<<dim3(12, 1024), 256, gemm_smem0>>>(p_ahi, p_alo, p_whi, p_wlo, bih0, p_gi, D_);

    // fused two-layer scan (layer 1 lags layer 0 by one step)
    reset_bar<<<1, 128>>>();
    gru_fused<<<128, 256, fused_smem>>>(p_gi, Whh0, bhh0, Wih1, bih1, Whh1, bhh1);

    // classifier on final hidden state
    fc_kernel<<<B_, 32>>>(p_hl, Wfc, bfc, out);
}

// round 14
// speedup vs baseline: 2.2079x; 1.2445x over previous
#include <cuda_runtime.h>
#include <cuda_bf16.h>
#include <math.h>
#include <stdint.h>

#define B_  256
#define T_  512
#define D_  128
#define H_  256
#define G_  768
#define C_  10

// ---------------- warp-mma helpers (sm_80+ baseline; compiles for plain sm_103) ---
__device__ __forceinline__ uint32_t smem_u32(const void* p) {
    uint32_t a;
    asm("{ .reg .u64 t; cvta.to.shared.u64 t, %1; cvt.u32.u64 %0, t; }" : "=r"(a) : "l"(p));
    return a;
}
#define LDSM4(r0, r1, r2, r3, addr) \
    asm volatile("ldmatrix.sync.aligned.m8n8.x4.shared.b16 {%0,%1,%2,%3}, [%4];" \
        : "=r"(r0), "=r"(r1), "=r"(r2), "=r"(r3) : "r"(addr))
#define MMA16816(c, a, b0v, b1v) \
    asm volatile("mma.sync.aligned.m16n8k16.row.col.f32.bf16.bf16.f32 " \
        "{%0,%1,%2,%3},{%4,%5,%6,%7},{%8,%9},{%0,%1,%2,%3};" \
        : "+f"((c)[0]), "+f"((c)[1]), "+f"((c)[2]), "+f"((c)[3]) \
        : "r"((a)[0]), "r"((a)[1]), "r"((a)[2]), "r"((a)[3]), "r"(b0v), "r"(b1v))

// ---------------- scratch (device globals; no allocation allowed) ----------------
__device__ __nv_bfloat16 g_seqhi[(size_t)T_ * B_ * H_]; // layer-0 h sequence, bf16 hi
__device__ __nv_bfloat16 g_seqlo[(size_t)T_ * B_ * H_]; // layer-0 h sequence, bf16 lo
__device__ __nv_bfloat16 g_hbhi[2][B_ * H_];            // layer-1 h ping-pong (hi)
__device__ __nv_bfloat16 g_hblo[2][B_ * H_];            // layer-1 h ping-pong (lo)
__device__ float g_hlast[B_ * H_];                      // final fp32 h2 for the FC
__device__ volatile unsigned g_gen0[4 * 32];            // layer-0 group generation
__device__ unsigned g_cnt0[4 * 32];
__device__ volatile unsigned g_gen1[4 * 32];            // layer-1 group generation
__device__ unsigned g_cnt1[4 * 32];
__device__ __nv_bfloat16 g_xhi[(size_t)B_ * T_ * D_];   // x split, bf16 hi
__device__ __nv_bfloat16 g_xlo[(size_t)B_ * T_ * D_];   // x split, bf16 lo

// ---------------- reset barrier state (graph-replay safe) --------------------------
__global__ void reset_bar()
{
    const int i = threadIdx.x;
    if (i < 128) {
        g_cnt0[i] = 0u; ((unsigned*)g_gen0)[i] = 0u;
        g_cnt1[i] = 0u; ((unsigned*)g_gen1)[i] = 0u;
    }
}

// ---------------- fp32 -> (bf16 hi, bf16 lo) split ---------------------------------
__global__ void split_bf16(const float* __restrict__ s, __nv_bfloat16* __restrict__ hi,
                           __nv_bfloat16* __restrict__ lo, int n4)
{
    const int i = blockIdx.x * blockDim.x + threadIdx.x;
    if (i >= n4) return;
    const float4 v = ((const float4*)s)[i];
    __nv_bfloat16 h0 = __float2bfloat16(v.x);
    __nv_bfloat16 h1 = __float2bfloat16(v.y);
    __nv_bfloat16 h2 = __float2bfloat16(v.z);
    __nv_bfloat16 h3 = __float2bfloat16(v.w);
    __nv_bfloat16 l0 = __float2bfloat16(v.x - __bfloat162float(h0));
    __nv_bfloat16 l1 = __float2bfloat16(v.y - __bfloat162float(h1));
    __nv_bfloat16 l2 = __float2bfloat16(v.z - __bfloat162float(h2));
    __nv_bfloat16 l3 = __float2bfloat16(v.w - __bfloat162float(h3));
    __nv_bfloat162* hp = (__nv_bfloat162*)hi;
    __nv_bfloat162* lp = (__nv_bfloat162*)lo;
    hp[i * 2 + 0] = __nv_bfloat162(h0, h1);
    hp[i * 2 + 1] = __nv_bfloat162(h2, h3);
    lp[i * 2 + 0] = __nv_bfloat162(l0, l1);
    lp[i * 2 + 1] = __nv_bfloat162(l2, l3);
}

// ---------------- fully fused two-layer GRU (no precomputed gi at all) -------------
// 128 CTAs x 256 threads. CTA<64: layer 0; CTA>=64: layer 1 (lags one step).
// Per-layer partition: 4 batch-groups x 16 jblk; CTA = 64 batches x 16 hidden dims
// (48 gate rows). Both layers run the same 2-phase step:
//   phase A: stage A-input (layer0: x(t) bf16-split, K=128; layer1: h1(t) from seq,
//            K=256), GEMM vs smem-resident Wih slice -> acc[0..5]
//   phase B: stage h_prev (layer0: seq[t-1]; layer1: h2 ping-pong), GEMM vs Whh
//            slice -> rz tiles into acc[0..3], n tiles into accN
//   gates -> publish (layer0 -> seq[t]; layer1 -> ping-pong + hlast)
// Sync: per-layer 16-CTA group barriers; layer-1 additionally waits gen0 >= t+1.
// smem: sihA hi 0 / lo 25344; shh hi 50688 / lo 76032; stageA hi 101376 / lo 135168;
//       part 168960/25088; partN 194048/8704; hst 202752/4352; bih 207104; bhh 207296.
__global__ void __launch_bounds__(256, 1) gru_fused2(
    const float* __restrict__ Wih0, const float* __restrict__ bih0,
    const float* __restrict__ Whh0, const float* __restrict__ bhh0,
    const float* __restrict__ Wih1, const float* __restrict__ bih1,
    const float* __restrict__ Whh1, const float* __restrict__ bhh1)
{
    extern __shared__ char smc[];
    __nv_bfloat16* sih_h = (__nv_bfloat16*)smc;
    __nv_bfloat16* sih_l = (__nv_bfloat16*)(smc + 25344);
    __nv_bfloat16* shh_h = (__nv_bfloat16*)(smc + 50688);
    __nv_bfloat16* shh_l = (__nv_bfloat16*)(smc + 76032);
    char* sthi = smc + 101376;
    char* stlo = smc + 135168;
    float* part  = (float*)(smc + 168960);
    float* partN = (float*)(smc + 194048);
    float* hst   = (float*)(smc + 202752);
    float* bih   = (float*)(smc + 207104);
    float* bhh   = (float*)(smc + 207296);

    const int tid = threadIdx.x;
    const int cta = blockIdx.x;
    const int layer = cta >> 6;
    const int lid = cta & 63;
    const int bblk = lid >> 4, jblk = lid & 15;
    const int b0 = bblk * 64, j0 = jblk * 16;
    const int slot = bblk * 32;

    const float* WA = layer ? Wih1 : Wih0;
    const float* WB = layer ? Whh1 : Whh0;
    const float* bA = layer ? bih1 : bih0;
    const float* bB = layer ? bhh1 : bhh0;
    const int KA = layer ? 256 : 128;          // phase-A K
    const int nksA = layer ? 8 : 4;
    volatile unsigned* genp = layer ? g_gen1 : g_gen0;
    unsigned* cntp = layer ? g_cnt1 : g_cnt0;

    // ---- load + split weight slices (48 gate rows each) ----
    for (int idx = tid; idx < 48 * KA; idx += 256) {
        const int row = idx / KA, k = idx % KA;
        const float v = WA[(size_t)((row >> 4) * H_ + j0 + (row & 15)) * KA + k];
        const __nv_bfloat16 hi = __float2bfloat16(v);
        sih_h[row * 264 + k] = hi;
        sih_l[row * 264 + k] = __float2bfloat16(v - __bfloat162float(hi));
    }
    for (int idx = tid; idx < 48 * 256; idx += 256) {
        const int row = idx >> 8, k = idx & 255;
        const float v = WB[(size_t)((row >> 4) * H_ + j0 + (row & 15)) * H_ + k];
        const __nv_bfloat16 hi = __float2bfloat16(v);
        shh_h[row * 264 + k] = hi;
        shh_l[row * 264 + k] = __float2bfloat16(v - __bfloat162float(hi));
    }
    if (tid < 48) {
        bih[tid] = bA[(tid >> 4) * H_ + j0 + (tid & 15)];
        bhh[tid] = bB[(tid >> 4) * H_ + j0 + (tid & 15)];
    }
    for (int idx = tid; idx < 64 * 17; idx += 256) hst[idx] = 0.f;

    const int w = tid >> 5, lane = tid & 31;
    const int mt = w & 3, kh = w >> 2;
    const int aoff = (mt * 16 + (lane & 15)) * 528 + (lane >> 4) * 16;
    const int brow = (lane & 7) + ((lane >> 4) << 3);
    const int bko  = ((lane >> 3) & 1) * 16;
    const uint32_t uSth = smem_u32(sthi), uStl = smem_u32(stlo);
    const uint32_t uIhi = smem_u32(smc), uIlo = smem_u32(smc + 25344);
    const uint32_t uHhi = smem_u32(smc + 50688), uHlo = smem_u32(smc + 76032);
    __syncthreads();

    for (int t = 0; t < T_; t++) {
        const int cur = t & 1, nxt = cur ^ 1;

        // layer-1 waits for layer-0 to have produced h1(t)
        if (layer == 1) {
            if (tid == 0) {
                while (g_gen0[slot] < (unsigned)(t + 1)) {}
                __threadfence();
            }
            __syncthreads();
        }

        // ---- phase A: stage A-input, GEMM vs Wih slice ----
        if (layer == 0) {
            // x(t): 64 rows x 128 bf16 (16 uint4/row)
#pragma unroll
            for (int q = 0; q < 4; q++) {
                const int v = tid + 256 * q;
                const int b = v >> 4, c = v & 15;
                const size_t so = ((size_t)(b0 + b) * T_ + t) * D_ + c * 8;
                *(uint4*)(sthi + b * 528 + c * 16) = *(const uint4*)&g_xhi[so];
                *(uint4*)(stlo + b * 528 + c * 16) = *(const uint4*)&g_xlo[so];
            }
        } else {
            // h1(t): 64 rows x 256 bf16 (32 uint4/row)
#pragma unroll
            for (int q = 0; q < 8; q++) {
                const int v = tid + 256 * q;
                const int b = v >> 5, c = v & 31;
                const size_t so = ((size_t)t * B_ + b0 + b) * H_ + c * 8;
                *(uint4*)(sthi + b * 528 + c * 16) = *(const uint4*)&g_seqhi[so];
                *(uint4*)(stlo + b * 528 + c * 16) = *(const uint4*)&g_seqlo[so];
            }
        }
        __syncthreads();

        float acc[6][4], accN[2][4];
#pragma unroll
        for (int nt = 0; nt < 6; nt++)
#pragma unroll
            for (int q = 0; q < 4; q++) acc[nt][q] = 0.f;
#pragma unroll
        for (int nt = 0; nt < 2; nt++)
#pragma unroll
            for (int q = 0; q < 4; q++) accN[nt][q] = 0.f;

        const int kbaseA = kh * (KA);        // bytes: half-K of KA elems * 2B
#pragma unroll 4
        for (int ks = 0; ks < nksA; ks++) {
            const int kb = kbaseA + ks * 32;
            uint32_t ah[4], al[4], bh[6][2], bl[6][2];
            LDSM4(ah[0], ah[1], ah[2], ah[3], uSth + aoff + kb);
            LDSM4(al[0], al[1], al[2], al[3], uStl + aoff + kb);
#pragma unroll
            for (int p = 0; p < 3; p++) {
                const uint32_t rb = (uint32_t)((p * 16 + brow) * 528 + bko + kb);
                uint32_t t0, t1, t2, t3;
                LDSM4(t0, t1, t2, t3, uIhi + rb);
                bh[p * 2][0] = t0; bh[p * 2][1] = t1;
                bh[p * 2 + 1][0] = t2; bh[p * 2 + 1][1] = t3;
                LDSM4(t0, t1, t2, t3, uIlo + rb);
                bl[p * 2][0] = t0; bl[p * 2][1] = t1;
                bl[p * 2 + 1][0] = t2; bl[p * 2 + 1][1] = t3;
            }
#pragma unroll
            for (int nt = 0; nt < 6; nt++) {
                MMA16816(acc[nt], ah, bh[nt][0], bh[nt][1]);
                MMA16816(acc[nt], ah, bl[nt][0], bl[nt][1]);
                MMA16816(acc[nt], al, bh[nt][0], bh[nt][1]);
            }
        }
        __syncthreads();   // before restaging the shared A buffer

        // ---- phase B: stage h_prev, GEMM vs Whh slice ----
        if (t == 0) {
            const uint4 z4 = make_uint4(0u, 0u, 0u, 0u);
#pragma unroll
            for (int q = 0; q < 8; q++) {
                const int v = tid + 256 * q;
                const int b = v >> 5, c = v & 31;
                *(uint4*)(sthi + b * 528 + c * 16) = z4;
                *(uint4*)(stlo + b * 528 + c * 16) = z4;
            }
        } else if (layer == 0) {
#pragma unroll
            for (int q = 0; q < 8; q++) {
                const int v = tid + 256 * q;
                const int b = v >> 5, c = v & 31;
                const size_t so = ((size_t)(t - 1) * B_ + b0 + b) * H_ + c * 8;
                *(uint4*)(sthi + b * 528 + c * 16) = *(const uint4*)&g_seqhi[so];
                *(uint4*)(stlo + b * 528 + c * 16) = *(const uint4*)&g_seqlo[so];
            }
        } else {
#pragma unroll
            for (int q = 0; q < 8; q++) {
                const int v = tid + 256 * q;
                const int b = v >> 5, c = v & 31;
                *(uint4*)(sthi + b * 528 + c * 16) =
                    *(const uint4*)&g_hbhi[cur][(b0 + b) * H_ + c * 8];
                *(uint4*)(stlo + b * 528 + c * 16) =
                    *(const uint4*)&g_hblo[cur][(b0 + b) * H_ + c * 8];
            }
        }
        __syncthreads();

#pragma unroll
        for (int ks = 0; ks < 8; ks++) {
            const int kb = kh * 256 + ks * 32;
            uint32_t ah[4], al[4], bh[6][2], bl[6][2];
            LDSM4(ah[0], ah[1], ah[2], ah[3], uSth + aoff + kb);
            LDSM4(al[0], al[1], al[2], al[3], uStl + aoff + kb);
#pragma unroll
            for (int p = 0; p < 3; p++) {
                const uint32_t rb = (uint32_t)((p * 16 + brow) * 528 + bko + kb);
                uint32_t t0, t1, t2, t3;
                LDSM4(t0, t1, t2, t3, uHhi + rb);
                bh[p * 2][0] = t0; bh[p * 2][1] = t1;
                bh[p * 2 + 1][0] = t2; bh[p * 2 + 1][1] = t3;
                LDSM4(t0, t1, t2, t3, uHlo + rb);
                bl[p * 2][0] = t0; bl[p * 2][1] = t1;
                bl[p * 2 + 1][0] = t2; bl[p * 2 + 1][1] = t3;
            }
#pragma unroll
            for (int nt = 0; nt < 4; nt++) {
                MMA16816(acc[nt], ah, bh[nt][0], bh[nt][1]);
                MMA16816(acc[nt], ah, bl[nt][0], bl[nt][1]);
                MMA16816(acc[nt], al, bh[nt][0], bh[nt][1]);
            }
#pragma unroll
            for (int nt = 4; nt < 6; nt++) {
                MMA16816(accN[nt - 4], ah, bh[nt][0], bh[nt][1]);
                MMA16816(accN[nt - 4], ah, bl[nt][0], bl[nt][1]);
                MMA16816(accN[nt - 4], al, bh[nt][0], bh[nt][1]);
            }
        }
        {
            const int prow = mt * 16 + (lane >> 2);
            float* pp = &part[(kh * 64 + prow) * 49];
            float* p8 = pp + 8 * 49;
            const int c2 = 2 * (lane & 3);
#pragma unroll
            for (int nt = 0; nt < 6; nt++) {
                pp[nt * 8 + c2] = acc[nt][0]; pp[nt * 8 + c2 + 1] = acc[nt][1];
                p8[nt * 8 + c2] = acc[nt][2]; p8[nt * 8 + c2 + 1] = acc[nt][3];
            }
            float* pn = &partN[kh * 1088 + prow * 17];
            float* pn8 = pn + 8 * 17;
#pragma unroll
            for (int nt = 0; nt < 2; nt++) {
                pn[nt * 8 + c2] = accN[nt][0]; pn[nt * 8 + c2 + 1] = accN[nt][1];
                pn8[nt * 8 + c2] = accN[nt][2]; pn8[nt * 8 + c2 + 1] = accN[nt][3];
            }
        }
        __syncthreads();

        // ---- gates: 4 (b,jj) per thread ----
        float vnew[4];
        int vb[4], vj[4];
#pragma unroll
        for (int p = 0; p < 4; p++) {
            const int pr = tid + p * 256;
            const int b = pr & 63, jj = pr >> 6;
            vb[p] = b; vj[p] = jj;
            const float* p0 = &part[b * 49];
            const float* p1 = &part[(64 + b) * 49];
            const float sr = bih[jj] + bhh[jj] + p0[jj] + p1[jj];
            const float sz = bih[16 + jj] + bhh[16 + jj] + p0[16 + jj] + p1[16 + jj];
            const float gin = bih[32 + jj] + p0[32 + jj] + p1[32 + jj];
            const float ghn = bhh[32 + jj]
                            + partN[b * 17 + jj] + partN[1088 + b * 17 + jj];
            const float r = __fdividef(1.f, 1.f + __expf(-sr));
            const float z = __fdividef(1.f, 1.f + __expf(-sz));
            const float a = gin + r * ghn;
            const float n = __fdividef(2.f, 1.f + __expf(-2.f * a)) - 1.f;
            vnew[p] = (1.f - z) * n + z * hst[b * 17 + jj];
        }
        __syncthreads();
#pragma unroll
        for (int p = 0; p < 4; p++) hst[vb[p] * 17 + vj[p]] = vnew[p];
        __syncthreads();

        // ---- publish h(t) ----
        if (tid < 128) {
            const int b = tid >> 1, seg = tid & 1;
            float f[8];
            union { __nv_bfloat16 a8[8]; uint4 u; } uhi, ulo;
#pragma unroll
            for (int j = 0; j < 8; j++) {
                f[j] = hst[b * 17 + seg * 8 + j];
                uhi.a8[j] = __float2bfloat16(f[j]);
                ulo.a8[j] = __float2bfloat16(f[j] - __bfloat162float(uhi.a8[j]));
            }
            if (layer == 0) {
                const size_t so = ((size_t)t * B_ + b0 + b) * H_ + j0 + seg * 8;
                *(uint4*)&g_seqhi[so] = uhi.u;
                *(uint4*)&g_seqlo[so] = ulo.u;
            } else {
                const size_t go = (size_t)(b0 + b) * H_ + j0 + seg * 8;
                *(uint4*)&g_hbhi[nxt][go] = uhi.u;
                *(uint4*)&g_hblo[nxt][go] = ulo.u;
                if (t == T_ - 1) {
                    *(float4*)&g_hlast[go]     = make_float4(f[0], f[1], f[2], f[3]);
                    *(float4*)&g_hlast[go + 4] = make_float4(f[4], f[5], f[6], f[7]);
                }
            }
        }

        // ---- per-layer 16-CTA group barrier ----
        __threadfence();
        __syncthreads();
        if (tid == 0) {
            const unsigned a = atomicAdd(&cntp[slot], 1u);
            if (a == 15u) {
                cntp[slot] = 0u;
                __threadfence();
                genp[slot] = (unsigned)(t + 1);
            } else {
                while (genp[slot] < (unsigned)(t + 1)) {}
            }
            __threadfence();
        }
        __syncthreads();
    }
}

// ---------------- final FC: out[256,10] = h @ Wfc^T + bfc -------------------------
__global__ void fc_kernel(const float* __restrict__ h, const float* __restrict__ Wfc,
                          const float* __restrict__ bfc, float* __restrict__ out)
{
    const int b = blockIdx.x;
    const int lane = threadIdx.x;
    float hv[8];
#pragma unroll
    for (int i = 0; i < 8; i++) hv[i] = h[b * H_ + lane + 32 * i];
    for (int cc = 0; cc < C_; cc++) {
        float s = 0.f;
#pragma unroll
        for (int i = 0; i < 8; i++) s += hv[i] * Wfc[cc * H_ + lane + 32 * i];
#pragma unroll
        for (int o = 16; o > 0; o >>= 1) s += __shfl_down_sync(0xffffffffu, s, o);
        if (lane == 0) out[b * C_ + cc] = s + bfc[cc];
    }
}

// ---------------- launch ----------------------------------------------------------
extern "C" void kernel_launch(void* const* d_in, const int* in_sizes, int n_in,
                              void* d_out, int out_size)
{
    (void)in_sizes; (void)n_in; (void)out_size;
    const float* x    = (const float*)d_in[0];
    const float* Wih0 = (const float*)d_in[1];
    const float* Whh0 = (const float*)d_in[2];
    const float* bih0 = (const float*)d_in[3];
    const float* bhh0 = (const float*)d_in[4];
    const float* Wih1 = (const float*)d_in[5];
    const float* Whh1 = (const float*)d_in[6];
    const float* bih1 = (const float*)d_in[7];
    const float* bhh1 = (const float*)d_in[8];
    const float* Wfc  = (const float*)d_in[9];
    const float* bfc  = (const float*)d_in[10];
    float* out = (float*)d_out;

    float* p_hl;
    __nv_bfloat16 *p_xhi, *p_xlo;
    cudaGetSymbolAddress((void**)&p_hl, g_hlast);
    cudaGetSymbolAddress((void**)&p_xhi, g_xhi);
    cudaGetSymbolAddress((void**)&p_xlo, g_xlo);

    const int fused_smem = 207488;
    cudaFuncSetAttribute(gru_fused2, cudaFuncAttributeMaxDynamicSharedMemorySize, fused_smem);

    // split x once (bf16 hi/lo); everything else happens in the fused scan
    split_bf16<<<(B_ * T_ * D_ / 4 + 255) / 256, 256>>>(x, p_xhi, p_xlo, B_ * T_ * D_ / 4);

    reset_bar<<<1, 128>>>();
    gru_fused2<<<128, 256, fused_smem>>>(Wih0, bih0, Whh0, bhh0,
                                         Wih1, bih1, Whh1, bhh1);

    // classifier on final hidden state
    fc_kernel<<<B_, 32>>>(p_hl, Wfc, bfc, out);
}

// round 15
// speedup vs baseline: 2.2351x; 1.0123x over previous
#include <cuda_runtime.h>
#include <cuda_bf16.h>
#include <math.h>
#include <stdint.h>

#define B_  256
#define T_  512
#define D_  128
#define H_  256
#define G_  768
#define C_  10

// ---------------- warp-mma helpers (sm_80+ baseline; compiles for plain sm_103) ---
__device__ __forceinline__ uint32_t smem_u32(const void* p) {
    uint32_t a;
    asm("{ .reg .u64 t; cvta.to.shared.u64 t, %1; cvt.u32.u64 %0, t; }" : "=r"(a) : "l"(p));
    return a;
}
#define LDSM4(r0, r1, r2, r3, addr) \
    asm volatile("ldmatrix.sync.aligned.m8n8.x4.shared.b16 {%0,%1,%2,%3}, [%4];" \
        : "=r"(r0), "=r"(r1), "=r"(r2), "=r"(r3) : "r"(addr))
#define MMA16816(c, a, b0v, b1v) \
    asm volatile("mma.sync.aligned.m16n8k16.row.col.f32.bf16.bf16.f32 " \
        "{%0,%1,%2,%3},{%4,%5,%6,%7},{%8,%9},{%0,%1,%2,%3};" \
        : "+f"((c)[0]), "+f"((c)[1]), "+f"((c)[2]), "+f"((c)[3]) \
        : "r"((a)[0]), "r"((a)[1]), "r"((a)[2]), "r"((a)[3]), "r"(b0v), "r"(b1v))

// ---------------- scratch (device globals; no allocation allowed) ----------------
__device__ __nv_bfloat16 g_seqhi[(size_t)T_ * B_ * H_]; // layer-0 h sequence, bf16 hi
__device__ __nv_bfloat16 g_seqlo[(size_t)T_ * B_ * H_]; // layer-0 h sequence, bf16 lo
__device__ __nv_bfloat16 g_hbhi[2][B_ * H_];            // layer-1 h ping-pong (hi)
__device__ __nv_bfloat16 g_hblo[2][B_ * H_];            // layer-1 h ping-pong (lo)
__device__ float g_hlast[B_ * H_];                      // final fp32 h2 for the FC
__device__ volatile unsigned g_gen0[4 * 32];            // layer-0 group generation
__device__ unsigned g_cnt0[4 * 32];
__device__ volatile unsigned g_gen1[4 * 32];            // layer-1 group generation
__device__ unsigned g_cnt1[4 * 32];
__device__ __nv_bfloat16 g_xhi[(size_t)B_ * T_ * D_];   // x split, bf16 hi
__device__ __nv_bfloat16 g_xlo[(size_t)B_ * T_ * D_];   // x split, bf16 lo

// ---------------- reset barrier state (graph-replay safe) --------------------------
__global__ void reset_bar()
{
    const int i = threadIdx.x;
    if (i < 128) {
        g_cnt0[i] = 0u; ((unsigned*)g_gen0)[i] = 0u;
        g_cnt1[i] = 0u; ((unsigned*)g_gen1)[i] = 0u;
    }
}

// ---------------- fp32 -> (bf16 hi, bf16 lo) split ---------------------------------
__global__ void split_bf16(const float* __restrict__ s, __nv_bfloat16* __restrict__ hi,
                           __nv_bfloat16* __restrict__ lo, int n4)
{
    const int i = blockIdx.x * blockDim.x + threadIdx.x;
    if (i >= n4) return;
    const float4 v = ((const float4*)s)[i];
    __nv_bfloat16 h0 = __float2bfloat16(v.x);
    __nv_bfloat16 h1 = __float2bfloat16(v.y);
    __nv_bfloat16 h2 = __float2bfloat16(v.z);
    __nv_bfloat16 h3 = __float2bfloat16(v.w);
    __nv_bfloat16 l0 = __float2bfloat16(v.x - __bfloat162float(h0));
    __nv_bfloat16 l1 = __float2bfloat16(v.y - __bfloat162float(h1));
    __nv_bfloat16 l2 = __float2bfloat16(v.z - __bfloat162float(h2));
    __nv_bfloat16 l3 = __float2bfloat16(v.w - __bfloat162float(h3));
    __nv_bfloat162* hp = (__nv_bfloat162*)hi;
    __nv_bfloat162* lp = (__nv_bfloat162*)lo;
    hp[i * 2 + 0] = __nv_bfloat162(h0, h1);
    hp[i * 2 + 1] = __nv_bfloat162(h2, h3);
    lp[i * 2 + 0] = __nv_bfloat162(l0, l1);
    lp[i * 2 + 1] = __nv_bfloat162(l2, l3);
}

// ---------------- fully fused two-layer GRU (R14 structure + latency cuts) ---------
// 128 CTAs x 256 threads. CTA<64: layer 0; CTA>=64: layer 1 (lags one step).
// Changes vs R14: (1) phase-B staging LDGs issued at iteration start into registers
// (source guaranteed ready by previous group barrier), STS'd after GEMM A — removes
// an exposed L2 round trip; (2) gates update hst in place (bijective ownership),
// dropping one __syncthreads and the vnew spill arrays.
__global__ void __launch_bounds__(256, 1) gru_fused2(
    const float* __restrict__ Wih0, const float* __restrict__ bih0,
    const float* __restrict__ Whh0, const float* __restrict__ bhh0,
    const float* __restrict__ Wih1, const float* __restrict__ bih1,
    const float* __restrict__ Whh1, const float* __restrict__ bhh1)
{
    extern __shared__ char smc[];
    __nv_bfloat16* sih_h = (__nv_bfloat16*)smc;
    __nv_bfloat16* sih_l = (__nv_bfloat16*)(smc + 25344);
    __nv_bfloat16* shh_h = (__nv_bfloat16*)(smc + 50688);
    __nv_bfloat16* shh_l = (__nv_bfloat16*)(smc + 76032);
    char* sthi = smc + 101376;
    char* stlo = smc + 135168;
    float* part  = (float*)(smc + 168960);
    float* partN = (float*)(smc + 194048);
    float* hst   = (float*)(smc + 202752);
    float* bih   = (float*)(smc + 207104);
    float* bhh   = (float*)(smc + 207296);

    const int tid = threadIdx.x;
    const int cta = blockIdx.x;
    const int layer = cta >> 6;
    const int lid = cta & 63;
    const int bblk = lid >> 4, jblk = lid & 15;
    const int b0 = bblk * 64, j0 = jblk * 16;
    const int slot = bblk * 32;

    const float* WA = layer ? Wih1 : Wih0;
    const float* WB = layer ? Whh1 : Whh0;
    const float* bA = layer ? bih1 : bih0;
    const float* bB = layer ? bhh1 : bhh0;
    const int KA = layer ? 256 : 128;          // phase-A K
    const int nksA = layer ? 8 : 4;
    volatile unsigned* genp = layer ? g_gen1 : g_gen0;
    unsigned* cntp = layer ? g_cnt1 : g_cnt0;

    // ---- load + split weight slices (48 gate rows each) ----
    for (int idx = tid; idx < 48 * KA; idx += 256) {
        const int row = idx / KA, k = idx % KA;
        const float v = WA[(size_t)((row >> 4) * H_ + j0 + (row & 15)) * KA + k];
        const __nv_bfloat16 hi = __float2bfloat16(v);
        sih_h[row * 264 + k] = hi;
        sih_l[row * 264 + k] = __float2bfloat16(v - __bfloat162float(hi));
    }
    for (int idx = tid; idx < 48 * 256; idx += 256) {
        const int row = idx >> 8, k = idx & 255;
        const float v = WB[(size_t)((row >> 4) * H_ + j0 + (row & 15)) * H_ + k];
        const __nv_bfloat16 hi = __float2bfloat16(v);
        shh_h[row * 264 + k] = hi;
        shh_l[row * 264 + k] = __float2bfloat16(v - __bfloat162float(hi));
    }
    if (tid < 48) {
        bih[tid] = bA[(tid >> 4) * H_ + j0 + (tid & 15)];
        bhh[tid] = bB[(tid >> 4) * H_ + j0 + (tid & 15)];
    }
    for (int idx = tid; idx < 64 * 17; idx += 256) hst[idx] = 0.f;

    const int w = tid >> 5, lane = tid & 31;
    const int mt = w & 3, kh = w >> 2;
    const int aoff = (mt * 16 + (lane & 15)) * 528 + (lane >> 4) * 16;
    const int brow = (lane & 7) + ((lane >> 4) << 3);
    const int bko  = ((lane >> 3) & 1) * 16;
    const uint32_t uSth = smem_u32(sthi), uStl = smem_u32(stlo);
    const uint32_t uIhi = smem_u32(smc), uIlo = smem_u32(smc + 25344);
    const uint32_t uHhi = smem_u32(smc + 50688), uHlo = smem_u32(smc + 76032);
    // fixed per-thread staging slot (b = v>>5, c = v&31 for v = tid + 256q)
    __syncthreads();

    for (int t = 0; t < T_; t++) {
        const int cur = t & 1, nxt = cur ^ 1;

        // layer-1 waits for layer-0 to have produced h1(t)
        if (layer == 1) {
            if (tid == 0) {
                while (g_gen0[slot] < (unsigned)(t + 1)) {}
                __threadfence();
            }
            __syncthreads();
        }

        // ---- prefetch phase-B staging into registers (covered by phase A) ----
        uint4 pfh[8], pfl[8];
        if (t == 0) {
            const uint4 z4 = make_uint4(0u, 0u, 0u, 0u);
#pragma unroll
            for (int q = 0; q < 8; q++) { pfh[q] = z4; pfl[q] = z4; }
        } else if (layer == 0) {
#pragma unroll
            for (int q = 0; q < 8; q++) {
                const int v = tid + 256 * q;
                const int b = v >> 5, c = v & 31;
                const size_t so = ((size_t)(t - 1) * B_ + b0 + b) * H_ + c * 8;
                pfh[q] = *(const uint4*)&g_seqhi[so];
                pfl[q] = *(const uint4*)&g_seqlo[so];
            }
        } else {
#pragma unroll
            for (int q = 0; q < 8; q++) {
                const int v = tid + 256 * q;
                const int b = v >> 5, c = v & 31;
                pfh[q] = *(const uint4*)&g_hbhi[cur][(b0 + b) * H_ + c * 8];
                pfl[q] = *(const uint4*)&g_hblo[cur][(b0 + b) * H_ + c * 8];
            }
        }

        // ---- phase A: stage A-input, GEMM vs Wih slice ----
        if (layer == 0) {
#pragma unroll
            for (int q = 0; q < 4; q++) {
                const int v = tid + 256 * q;
                const int b = v >> 4, c = v & 15;
                const size_t so = ((size_t)(b0 + b) * T_ + t) * D_ + c * 8;
                *(uint4*)(sthi + b * 528 + c * 16) = *(const uint4*)&g_xhi[so];
                *(uint4*)(stlo + b * 528 + c * 16) = *(const uint4*)&g_xlo[so];
            }
        } else {
#pragma unroll
            for (int q = 0; q < 8; q++) {
                const int v = tid + 256 * q;
                const int b = v >> 5, c = v & 31;
                const size_t so = ((size_t)t * B_ + b0 + b) * H_ + c * 8;
                *(uint4*)(sthi + b * 528 + c * 16) = *(const uint4*)&g_seqhi[so];
                *(uint4*)(stlo + b * 528 + c * 16) = *(const uint4*)&g_seqlo[so];
            }
        }
        __syncthreads();

        float acc[6][4], accN[2][4];
#pragma unroll
        for (int nt = 0; nt < 6; nt++)
#pragma unroll
            for (int q = 0; q < 4; q++) acc[nt][q] = 0.f;
#pragma unroll
        for (int nt = 0; nt < 2; nt++)
#pragma unroll
            for (int q = 0; q < 4; q++) accN[nt][q] = 0.f;

        const int kbaseA = kh * KA;          // byte offset of this warp's K-half
#pragma unroll 4
        for (int ks = 0; ks < nksA; ks++) {
            const int kb = kbaseA + ks * 32;
            uint32_t ah[4], al[4], bh[6][2], bl[6][2];
            LDSM4(ah[0], ah[1], ah[2], ah[3], uSth + aoff + kb);
            LDSM4(al[0], al[1], al[2], al[3], uStl + aoff + kb);
#pragma unroll
            for (int p = 0; p < 3; p++) {
                const uint32_t rb = (uint32_t)((p * 16 + brow) * 528 + bko + kb);
                uint32_t t0, t1, t2, t3;
                LDSM4(t0, t1, t2, t3, uIhi + rb);
                bh[p * 2][0] = t0; bh[p * 2][1] = t1;
                bh[p * 2 + 1][0] = t2; bh[p * 2 + 1][1] = t3;
                LDSM4(t0, t1, t2, t3, uIlo + rb);
                bl[p * 2][0] = t0; bl[p * 2][1] = t1;
                bl[p * 2 + 1][0] = t2; bl[p * 2 + 1][1] = t3;
            }
#pragma unroll
            for (int nt = 0; nt < 6; nt++) {
                MMA16816(acc[nt], ah, bh[nt][0], bh[nt][1]);
                MMA16816(acc[nt], ah, bl[nt][0], bl[nt][1]);
                MMA16816(acc[nt], al, bh[nt][0], bh[nt][1]);
            }
        }
        __syncthreads();   // phase-A reads of stage buffer complete

        // ---- phase B: store prefetched h_prev (STS only), GEMM vs Whh slice ----
#pragma unroll
        for (int q = 0; q < 8; q++) {
            const int v = tid + 256 * q;
            const int b = v >> 5, c = v & 31;
            *(uint4*)(sthi + b * 528 + c * 16) = pfh[q];
            *(uint4*)(stlo + b * 528 + c * 16) = pfl[q];
        }
        __syncthreads();

#pragma unroll
        for (int ks = 0; ks < 8; ks++) {
            const int kb = kh * 256 + ks * 32;
            uint32_t ah[4], al[4], bh[6][2], bl[6][2];
            LDSM4(ah[0], ah[1], ah[2], ah[3], uSth + aoff + kb);
            LDSM4(al[0], al[1], al[2], al[3], uStl + aoff + kb);
#pragma unroll
            for (int p = 0; p < 3; p++) {
                const uint32_t rb = (uint32_t)((p * 16 + brow) * 528 + bko + kb);
                uint32_t t0, t1, t2, t3;
                LDSM4(t0, t1, t2, t3, uHhi + rb);
                bh[p * 2][0] = t0; bh[p * 2][1] = t1;
                bh[p * 2 + 1][0] = t2; bh[p * 2 + 1][1] = t3;
                LDSM4(t0, t1, t2, t3, uHlo + rb);
                bl[p * 2][0] = t0; bl[p * 2][1] = t1;
                bl[p * 2 + 1][0] = t2; bl[p * 2 + 1][1] = t3;
            }
#pragma unroll
            for (int nt = 0; nt < 4; nt++) {
                MMA16816(acc[nt], ah, bh[nt][0], bh[nt][1]);
                MMA16816(acc[nt], ah, bl[nt][0], bl[nt][1]);
                MMA16816(acc[nt], al, bh[nt][0], bh[nt][1]);
            }
#pragma unroll
            for (int nt = 4; nt < 6; nt++) {
                MMA16816(accN[nt - 4], ah, bh[nt][0], bh[nt][1]);
                MMA16816(accN[nt - 4], ah, bl[nt][0], bl[nt][1]);
                MMA16816(accN[nt - 4], al, bh[nt][0], bh[nt][1]);
            }
        }
        {
            const int prow = mt * 16 + (lane >> 2);
            float* pp = &part[(kh * 64 + prow) * 49];
            float* p8 = pp + 8 * 49;
            const int c2 = 2 * (lane & 3);
#pragma unroll
            for (int nt = 0; nt < 6; nt++) {
                pp[nt * 8 + c2] = acc[nt][0]; pp[nt * 8 + c2 + 1] = acc[nt][1];
                p8[nt * 8 + c2] = acc[nt][2]; p8[nt * 8 + c2 + 1] = acc[nt][3];
            }
            float* pn = &partN[kh * 1088 + prow * 17];
            float* pn8 = pn + 8 * 17;
#pragma unroll
            for (int nt = 0; nt < 2; nt++) {
                pn[nt * 8 + c2] = accN[nt][0]; pn[nt * 8 + c2 + 1] = accN[nt][1];
                pn8[nt * 8 + c2] = accN[nt][2]; pn8[nt * 8 + c2 + 1] = accN[nt][3];
            }
        }
        __syncthreads();

        // ---- gates: 4 (b,jj) per thread, in-place hst update (exclusive owner) ----
#pragma unroll
        for (int p = 0; p < 4; p++) {
            const int pr = tid + p * 256;
            const int b = pr & 63, jj = pr >> 6;
            const float* p0 = &part[b * 49];
            const float* p1 = &part[(64 + b) * 49];
            const float sr = bih[jj] + bhh[jj] + p0[jj] + p1[jj];
            const float sz = bih[16 + jj] + bhh[16 + jj] + p0[16 + jj] + p1[16 + jj];
            const float gin = bih[32 + jj] + p0[32 + jj] + p1[32 + jj];
            const float ghn = bhh[32 + jj]
                            + partN[b * 17 + jj] + partN[1088 + b * 17 + jj];
            const float r = __fdividef(1.f, 1.f + __expf(-sr));
            const float z = __fdividef(1.f, 1.f + __expf(-sz));
            const float a = gin + r * ghn;
            const float n = __fdividef(2.f, 1.f + __expf(-2.f * a)) - 1.f;
            hst[b * 17 + jj] = (1.f - z) * n + z * hst[b * 17 + jj];
        }
        __syncthreads();

        // ---- publish h(t) ----
        if (tid < 128) {
            const int b = tid >> 1, seg = tid & 1;
            float f[8];
            union { __nv_bfloat16 a8[8]; uint4 u; } uhi, ulo;
#pragma unroll
            for (int j = 0; j < 8; j++) {
                f[j] = hst[b * 17 + seg * 8 + j];
                uhi.a8[j] = __float2bfloat16(f[j]);
                ulo.a8[j] = __float2bfloat16(f[j] - __bfloat162float(uhi.a8[j]));
            }
            if (layer == 0) {
                const size_t so = ((size_t)t * B_ + b0 + b) * H_ + j0 + seg * 8;
                *(uint4*)&g_seqhi[so] = uhi.u;
                *(uint4*)&g_seqlo[so] = ulo.u;
            } else {
                const size_t go = (size_t)(b0 + b) * H_ + j0 + seg * 8;
                *(uint4*)&g_hbhi[nxt][go] = uhi.u;
                *(uint4*)&g_hblo[nxt][go] = ulo.u;
                if (t == T_ - 1) {
                    *(float4*)&g_hlast[go]     = make_float4(f[0], f[1], f[2], f[3]);
                    *(float4*)&g_hlast[go + 4] = make_float4(f[4], f[5], f[6], f[7]);
                }
            }
        }

        // ---- per-layer 16-CTA group barrier ----
        __threadfence();
        __syncthreads();
        if (tid == 0) {
            const unsigned a = atomicAdd(&cntp[slot], 1u);
            if (a == 15u) {
                cntp[slot] = 0u;
                __threadfence();
                genp[slot] = (unsigned)(t + 1);
            } else {
                while (genp[slot] < (unsigned)(t + 1)) {}
            }
            __threadfence();
        }
        __syncthreads();
    }
}

// ---------------- final FC: out[256,10] = h @ Wfc^T + bfc -------------------------
__global__ void fc_kernel(const float* __restrict__ h, const float* __restrict__ Wfc,
                          const float* __restrict__ bfc, float* __restrict__ out)
{
    const int b = blockIdx.x;
    const int lane = threadIdx.x;
    float hv[8];
#pragma unroll
    for (int i = 0; i < 8; i++) hv[i] = h[b * H_ + lane + 32 * i];
    for (int cc = 0; cc < C_; cc++) {
        float s = 0.f;
#pragma unroll
        for (int i = 0; i < 8; i++) s += hv[i] * Wfc[cc * H_ + lane + 32 * i];
#pragma unroll
        for (int o = 16; o > 0; o >>= 1) s += __shfl_down_sync(0xffffffffu, s, o);
        if (lane == 0) out[b * C_ + cc] = s + bfc[cc];
    }
}

// ---------------- launch ----------------------------------------------------------
extern "C" void kernel_launch(void* const* d_in, const int* in_sizes, int n_in,
                              void* d_out, int out_size)
{
    (void)in_sizes; (void)n_in; (void)out_size;
    const float* x    = (const float*)d_in[0];
    const float* Wih0 = (const float*)d_in[1];
    const float* Whh0 = (const float*)d_in[2];
    const float* bih0 = (const float*)d_in[3];
    const float* bhh0 = (const float*)d_in[4];
    const float* Wih1 = (const float*)d_in[5];
    const float* Whh1 = (const float*)d_in[6];
    const float* bih1 = (const float*)d_in[7];
    const float* bhh1 = (const float*)d_in[8];
    const float* Wfc  = (const float*)d_in[9];
    const float* bfc  = (const float*)d_in[10];
    float* out = (float*)d_out;

    float* p_hl;
    __nv_bfloat16 *p_xhi, *p_xlo;
    cudaGetSymbolAddress((void**)&p_hl, g_hlast);
    cudaGetSymbolAddress((void**)&p_xhi, g_xhi);
    cudaGetSymbolAddress((void**)&p_xlo, g_xlo);

    const int fused_smem = 207488;
    cudaFuncSetAttribute(gru_fused2, cudaFuncAttributeMaxDynamicSharedMemorySize, fused_smem);

    // split x once (bf16 hi/lo); everything else happens in the fused scan
    split_bf16<<<(B_ * T_ * D_ / 4 + 255) / 256, 256>>>(x, p_xhi, p_xlo, B_ * T_ * D_ / 4);

    reset_bar<<<1, 128>>>();
    gru_fused2<<<128, 256, fused_smem>>>(Wih0, bih0, Whh0, bhh0,
                                         Wih1, bih1, Whh1, bhh1);

    // classifier on final hidden state
    fc_kernel<<<B_, 32>>>(p_hl, Wfc, bfc, out);
}